// round 5
// baseline (speedup 1.0000x reference)
#include <cuda_runtime.h>
#include <math.h>

#define MAXN 50000
#define MAXE 800000

// ---- device scratch (allocation-free rule) ----
__device__ float g_P[MAXN * 64];      // s @ ng_w1[0:64]
__device__ float g_z[MAXN * 128];     // segsum(silu(hm))
__device__ float g_vagg[MAXN * 3];
__device__ float g_deg[MAXN];
__device__ float g_Wpt[128 * 192];    // fused W' transposed: [o][r]
__device__ float g_b1p[128];          // fused bias into hm
__device__ float g_q[128];            // mg_w2 @ pe_w
__device__ float g_qb[1];             // b_mg2 @ pe_w + pe_b

__device__ __forceinline__ float siluf(float x) { return x / (1.0f + __expf(-x)); }

__device__ __forceinline__ void reds(float* p, float v) {
    asm volatile("red.global.add.f32 [%0], %1;" :: "l"(p), "f"(v) : "memory");
}
__device__ __forceinline__ void barrow(int id) {
    asm volatile("bar.sync %0, 64;" :: "r"(id) : "memory");
}

// ---- packed f32x2 helpers (Blackwell) ----
typedef unsigned long long u64t;
__device__ __forceinline__ u64t pack2(float x, float y) {
    u64t r; asm("mov.b64 %0, {%1,%2};" : "=l"(r) : "f"(x), "f"(y)); return r;
}
__device__ __forceinline__ float2 unpack2(u64t v) {
    float2 r; asm("mov.b64 {%0,%1}, %2;" : "=f"(r.x), "=f"(r.y) : "l"(v)); return r;
}
__device__ __forceinline__ void ffma2(u64t& d, u64t a, u64t b) {
    asm("fma.rn.f32x2 %0, %1, %2, %0;" : "+l"(d) : "l"(a), "l"(b));
}

// ---------------------------------------------------------------- zero scratch
__global__ void zero_kernel(int n128, int n3, int n1) {
    int i = blockIdx.x * blockDim.x + threadIdx.x;
    int stride = gridDim.x * blockDim.x;
    for (int k = i; k < n128; k += stride) g_z[k] = 0.0f;
    for (int k = i; k < n3; k += stride) g_vagg[k] = 0.0f;
    for (int k = i; k < n1; k += stride) g_deg[k] = 0.0f;
}

// ---------------------------------------------------------------- P = s @ ng_w1[0:64,:]
__global__ __launch_bounds__(256) void pre_kernel(const float* __restrict__ s,
                                                  const float* __restrict__ ngw1, int N) {
    __shared__ float wt[64][68];
    __shared__ float xs[4][68];
    const int tid = threadIdx.x;
    for (int idx = tid; idx < 64 * 64; idx += 256) {
        int k = idx >> 6, f = idx & 63;
        wt[f][k] = ngw1[idx];
    }
    __syncthreads();
    const int slot = tid >> 6, f = tid & 63;
    for (int n0 = blockIdx.x * 4; n0 < N; n0 += gridDim.x * 4) {
        int n = n0 + slot;
        xs[slot][f] = (n < N) ? s[n * 64 + f] : 0.0f;
        __syncthreads();
        float acc = 0.0f;
#pragma unroll 4
        for (int k = 0; k < 64; k += 4) {
            float4 w = *(const float4*)&wt[f][k];
            float4 x = *(const float4*)&xs[slot][k];
            acc += w.x * x.x + w.y * x.y + w.z * x.z + w.w * x.w;
        }
        if (n < N) g_P[n * 64 + f] = acc;
        __syncthreads();
    }
}

// ---------------------------------------------------------------- fold weights
__global__ void preW_kernel(const float* __restrict__ ngw2, const float* __restrict__ ngb2,
                            const float* __restrict__ egw2, const float* __restrict__ egb2,
                            const float* __restrict__ mgw1, const float* __restrict__ mgb1,
                            const float* __restrict__ mgw2, const float* __restrict__ mgb2,
                            const float* __restrict__ pew, const float* __restrict__ peb) {
    int idx = blockIdx.x * blockDim.x + threadIdx.x;
    int stride = gridDim.x * blockDim.x;
    for (int t = idx; t < 128 * 192 + 128 + 128 + 1; t += stride) {
        if (t < 128 * 192) {
            int o = t / 192, r = t % 192;
            int seg = r >> 6, rr = r & 63, koff = seg * 64;
            const float* src = (seg < 2) ? ngw2 : egw2;
            float val = 0.0f;
            for (int k = 0; k < 64; k++)
                val += src[rr * 64 + k] * mgw1[(koff + k) * 128 + o];
            g_Wpt[o * 192 + r] = val;
        } else if (t < 128 * 192 + 128) {
            int o = t - 128 * 192;
            float val = mgb1[o];
            for (int k = 0; k < 64; k++) {
                val += ngb2[k] * (mgw1[k * 128 + o] + mgw1[(64 + k) * 128 + o]);
                val += egb2[k] * mgw1[(128 + k) * 128 + o];
            }
            g_b1p[o] = val;
        } else if (t < 128 * 192 + 256) {
            int o = t - 128 * 192 - 128;
            float val = 0.0f;
            for (int j = 0; j < 64; j++) val += mgw2[o * 64 + j] * pew[j];
            g_q[o] = val;
        } else {
            float val = peb[0];
            for (int j = 0; j < 64; j++) val += mgb2[j] * pew[j];
            g_qb[0] = val;
        }
    }
}

// ---------------------------------------------------------------- fused edge kernel
// 512 threads = 8 independent rows x 64 lanes; each row owns 12 edges/tile (6 pairs).
// Cross-tile software prefetch hides LDG latency behind the S2 GEMM.
#define ROWS 8
#define EPR 12
#define NPAIR 6

struct __align__(16) EdgeSmem {
    float egw1t[64][68];               // eg_w1 transposed [f][k], k=0..64
    float wpt[128][196];               // fused W' transposed [o][r]
    float XP[ROWS][NPAIR][192][2];     // pair-interleaved X
    float EAP[ROWS][NPAIR][66][2];     // pair-interleaved edge_attr (+cross at k=64)
    float w65[64], bng1[64], beg1[64];
    float b1p[128], q[128];
    float resI[ROWS][EPR], resJ[ROWS][EPR];
    float evu_s[ROWS][EPR][3];
    int eRow[ROWS][EPR], eCol[ROWS][EPR], valid[ROWS][EPR];
    float qb;
};

__global__ __launch_bounds__(512) void edge_kernel(
    const float* __restrict__ v, const int* __restrict__ ei,
    const float* __restrict__ ea, const float* __restrict__ evu,
    const float* __restrict__ ngw1, const float* __restrict__ ngb1,
    const float* __restrict__ egw1, const float* __restrict__ egb1,
    int N, int E) {
    extern __shared__ char smem_raw[];
    EdgeSmem& sm = *reinterpret_cast<EdgeSmem*>(smem_raw);
    const int tid = threadIdx.x;

    // ---- one-time staging ----
    for (int idx = tid; idx < 65 * 64; idx += 512) {
        int k = idx >> 6, f = idx & 63;
        sm.egw1t[f][k] = egw1[idx];
    }
    for (int idx = tid; idx < 128 * 192; idx += 512) {
        int o = idx / 192, r = idx % 192;
        sm.wpt[o][r] = g_Wpt[idx];
    }
    if (tid < 64) {
        sm.w65[tid] = ngw1[64 * 64 + tid];
        sm.bng1[tid] = ngb1[tid];
        sm.beg1[tid] = egb1[tid];
    } else if (tid < 192) {
        sm.b1p[tid - 64] = g_b1p[tid - 64];
    } else if (tid < 320) {
        sm.q[tid - 192] = g_q[tid - 192];
    } else if (tid == 320) {
        sm.qb = g_qb[0];
    }
    __syncthreads();

    const int f = tid & 63;
    const int row = tid >> 6;        // 0..7
    const int lane = tid & 31;
    const int half = (tid >> 5) & 1;
    const float qbh = 0.5f * sm.qb;
    const int stride = gridDim.x * (ROWS * EPR);

    // hoisted per-lane constants / pointers
    const float begf = sm.beg1[f];
    const float w64v = sm.egw1t[f][64];
    const float w65v = sm.w65[f], b1v = sm.bng1[f];
    const float bA = sm.b1p[f], bB = sm.b1p[64 + f];
    const float qf = sm.q[f], qg = sm.q[64 + f];
    const float* egrow = sm.egw1t[f];
    const float* warow = sm.wpt[f];
    const float* wbrow = sm.wpt[64 + f];
    float (*XPr)[192][2] = sm.XP[row];
    float (*EAPr)[66][2] = sm.EAP[row];
    int* eRowR = sm.eRow[row];
    int* eColR = sm.eCol[row];
    int* validR = sm.valid[row];

    // ---- prefetch registers (consumed at next S0) ----
    float pfa[12];                       // 3 x (a0.x, a1.x, a0.y, a1.y)
    int pfr = 0, pfc = 0, pfok = 0;
    float pfu0 = 0.f, pfu1 = 0.f, pfu2 = 0.f;
    float pvi0 = 0.f, pvi1 = 0.f, pvi2 = 0.f;
    float pvj0 = 0.f, pvj1 = 0.f, pvj2 = 0.f;

    int base = blockIdx.x * (ROWS * EPR) + row * EPR;

    // ---- cold prefetch for first tile ----
    if (f < EPR) {
        int e = base + f;
        pfok = (e < E);
        if (pfok) {
            pfr = ei[e]; pfc = ei[E + e];
            pfu0 = evu[e * 3 + 0]; pfu1 = evu[e * 3 + 1]; pfu2 = evu[e * 3 + 2];
            pvi0 = v[pfr * 3 + 0]; pvi1 = v[pfr * 3 + 1]; pvi2 = v[pfr * 3 + 2];
            pvj0 = v[pfc * 3 + 0]; pvj1 = v[pfc * 3 + 1]; pvj2 = v[pfc * 3 + 2];
        }
    }
#pragma unroll
    for (int it = 0; it < 3; it++) {
        int idx = f + 64 * it;
        int p = idx >> 5, kk = (idx & 31) * 2;
        int e0 = base + 2 * p, e1 = e0 + 1;
        float2 a0 = make_float2(0.f, 0.f), a1 = a0;
        if (e0 < E) a0 = *(const float2*)&ea[(size_t)e0 * 64 + kk];
        if (e1 < E) a1 = *(const float2*)&ea[(size_t)e1 * 64 + kk];
        pfa[it * 4 + 0] = a0.x; pfa[it * 4 + 1] = a1.x;
        pfa[it * 4 + 2] = a0.y; pfa[it * 4 + 3] = a1.y;
    }

    for (; base < E; ) {
        // ---- S0: consume prefetched data into smem ----
        if (f < EPR) {
            validR[f] = pfok;
            if (pfok) {
                eRowR[f] = pfr; eColR[f] = pfc;
                sm.evu_s[row][f][0] = pfu0; sm.evu_s[row][f][1] = pfu1; sm.evu_s[row][f][2] = pfu2;
                sm.resI[row][f] = 1.0f - (pvi0 * pfu0 + pvi1 * pfu1 + pvi2 * pfu2);
                sm.resJ[row][f] = 1.0f + (pvj0 * pfu0 + pvj1 * pfu1 + pvj2 * pfu2);
                float cx = pvi1 * pvj2 - pvi2 * pvj1;
                float cy = pvi2 * pvj0 - pvi0 * pvj2;
                float cz = pvi0 * pvj1 - pvi1 * pvj0;
                EAPr[f >> 1][64][f & 1] = sqrtf(cx * cx + cy * cy + cz * cz);
            } else {
                eRowR[f] = 0; eColR[f] = 0;
                sm.resI[row][f] = 0.0f; sm.resJ[row][f] = 0.0f;
                EAPr[f >> 1][64][f & 1] = 0.0f;
                sm.evu_s[row][f][0] = sm.evu_s[row][f][1] = sm.evu_s[row][f][2] = 0.0f;
            }
        }
#pragma unroll
        for (int it = 0; it < 3; it++) {
            int idx = f + 64 * it;
            int p = idx >> 5, kk = (idx & 31) * 2;
            *(float4*)&EAPr[p][kk][0] =
                make_float4(pfa[it * 4 + 0], pfa[it * 4 + 1], pfa[it * 4 + 2], pfa[it * 4 + 3]);
        }

        const int nbase = base + stride;
        // ---- prefetch stage 1: ei + evu for next tile (flies during S1) ----
        if (f < EPR) {
            int e = nbase + f;
            pfok = (e < E);
            if (pfok) {
                pfr = ei[e]; pfc = ei[E + e];
                pfu0 = evu[e * 3 + 0]; pfu1 = evu[e * 3 + 1]; pfu2 = evu[e * 3 + 2];
            } else { pfr = 0; pfc = 0; pfu0 = pfu1 = pfu2 = 0.f; }
        }
        barrow(row);

        // ---- S1: h_e (packed GEMM), h_i/h_j via P ----
        {
            u64t aE[NPAIR];
            u64t binit = pack2(begf, begf);
#pragma unroll
            for (int p = 0; p < NPAIR; p++) aE[p] = binit;
#pragma unroll 4
            for (int k = 0; k < 64; k += 4) {
                float4 w = *(const float4*)&egrow[k];
                u64t w0 = pack2(w.x, w.x), w1 = pack2(w.y, w.y);
                u64t w2 = pack2(w.z, w.z), w3 = pack2(w.w, w.w);
#pragma unroll
                for (int p = 0; p < NPAIR; p++) {
                    ulonglong2 q0 = *(const ulonglong2*)&EAPr[p][k][0];
                    ulonglong2 q1 = *(const ulonglong2*)&EAPr[p][k + 2][0];
                    ffma2(aE[p], q0.x, w0);
                    ffma2(aE[p], q0.y, w1);
                    ffma2(aE[p], q1.x, w2);
                    ffma2(aE[p], q1.y, w3);
                }
            }
            u64t wc = pack2(w64v, w64v);
#pragma unroll
            for (int p = 0; p < NPAIR; p++) {
                u64t cr = *(const u64t*)&EAPr[p][64][0];
                ffma2(aE[p], cr, wc);
                float2 g = unpack2(aE[p]);
                float2 o; o.x = siluf(g.x); o.y = siluf(g.y);
                *(float2*)&XPr[p][128 + f][0] = o;
            }
        }
#pragma unroll
        for (int p = 0; p < NPAIR; p++) {
            int j0 = 2 * p, j1 = 2 * p + 1;
            float pi0 = 0.f, pi1 = 0.f, pj0 = 0.f, pj1 = 0.f;
            if (validR[j0]) { pi0 = g_P[eRowR[j0] * 64 + f]; pj0 = g_P[eColR[j0] * 64 + f]; }
            if (validR[j1]) { pi1 = g_P[eRowR[j1] * 64 + f]; pj1 = g_P[eColR[j1] * 64 + f]; }
            float2 hi, hj;
            hi.x = siluf(pi0 + sm.resI[row][j0] * w65v + b1v);
            hi.y = siluf(pi1 + sm.resI[row][j1] * w65v + b1v);
            hj.x = siluf(pj0 + sm.resJ[row][j0] * w65v + b1v);
            hj.y = siluf(pj1 + sm.resJ[row][j1] * w65v + b1v);
            *(float2*)&XPr[p][f][0] = hi;
            *(float2*)&XPr[p][64 + f][0] = hj;
        }
        barrow(row);

        // ---- prefetch stage 2: ea + v gathers for next tile (fly during S2) ----
#pragma unroll
        for (int it = 0; it < 3; it++) {
            int idx = f + 64 * it;
            int p = idx >> 5, kk = (idx & 31) * 2;
            int e0 = nbase + 2 * p, e1 = e0 + 1;
            float2 a0 = make_float2(0.f, 0.f), a1 = a0;
            if (e0 < E) a0 = *(const float2*)&ea[(size_t)e0 * 64 + kk];
            if (e1 < E) a1 = *(const float2*)&ea[(size_t)e1 * 64 + kk];
            pfa[it * 4 + 0] = a0.x; pfa[it * 4 + 1] = a1.x;
            pfa[it * 4 + 2] = a0.y; pfa[it * 4 + 3] = a1.y;
        }
        if (f < EPR && pfok) {
            pvi0 = v[pfr * 3 + 0]; pvi1 = v[pfr * 3 + 1]; pvi2 = v[pfr * 3 + 2];
            pvj0 = v[pfc * 3 + 0]; pvj1 = v[pfc * 3 + 1]; pvj2 = v[pfc * 3 + 2];
        }

        // ---- S2: hm = X @ W' + b1p (packed) ; g = silu ; RED g_z ; coeff ----
        {
            u64t accA[NPAIR], accB[NPAIR];
            u64t ia = pack2(bA, bA), ib = pack2(bB, bB);
#pragma unroll
            for (int p = 0; p < NPAIR; p++) { accA[p] = ia; accB[p] = ib; }
#pragma unroll 4
            for (int k = 0; k < 192; k += 4) {
                float4 wa = *(const float4*)&warow[k];
                float4 wb = *(const float4*)&wbrow[k];
                u64t wa0 = pack2(wa.x, wa.x), wa1 = pack2(wa.y, wa.y);
                u64t wa2 = pack2(wa.z, wa.z), wa3 = pack2(wa.w, wa.w);
                u64t wb0 = pack2(wb.x, wb.x), wb1 = pack2(wb.y, wb.y);
                u64t wb2 = pack2(wb.z, wb.z), wb3 = pack2(wb.w, wb.w);
#pragma unroll
                for (int p = 0; p < NPAIR; p++) {
                    ulonglong2 q0 = *(const ulonglong2*)&XPr[p][k][0];
                    ulonglong2 q1 = *(const ulonglong2*)&XPr[p][k + 2][0];
                    ffma2(accA[p], q0.x, wa0);
                    ffma2(accB[p], q0.x, wb0);
                    ffma2(accA[p], q0.y, wa1);
                    ffma2(accB[p], q0.y, wb1);
                    ffma2(accA[p], q1.x, wa2);
                    ffma2(accB[p], q1.x, wb2);
                    ffma2(accA[p], q1.y, wa3);
                    ffma2(accB[p], q1.y, wb3);
                }
            }
            float pco[EPR];
#pragma unroll
            for (int p = 0; p < NPAIR; p++) {
                float2 gA = unpack2(accA[p]);
                float2 gB = unpack2(accB[p]);
                gA.x = siluf(gA.x); gA.y = siluf(gA.y);
                gB.x = siluf(gB.x); gB.y = siluf(gB.y);
                int j0 = 2 * p, j1 = 2 * p + 1;
                if (validR[j0]) {
                    int dst = eRowR[j0];
                    reds(&g_z[dst * 128 + f], gA.x);
                    reds(&g_z[dst * 128 + 64 + f], gB.x);
                }
                if (validR[j1]) {
                    int dst = eRowR[j1];
                    reds(&g_z[dst * 128 + f], gA.y);
                    reds(&g_z[dst * 128 + 64 + f], gB.y);
                }
                pco[j0] = gA.x * qf + gB.x * qg;
                pco[j1] = gA.y * qf + gB.y * qg;
            }
#pragma unroll
            for (int j = 0; j < EPR; j++) {
#pragma unroll
                for (int off = 16; off > 0; off >>= 1)
                    pco[j] += __shfl_xor_sync(0xffffffffu, pco[j], off);
            }
            // each warp REDs qb/2 + its half-sum for every edge (3*EPR = 36 > 32 lanes)
            for (int t = lane; t < 3 * EPR; t += 32) {
                int j = t / 3, c = t % 3;
                if (validR[j]) {
                    float cf = qbh + pco[j];
                    reds(&g_vagg[eRowR[j] * 3 + c], sm.evu_s[row][j][c] * cf);
                }
            }
            if (half == 0 && lane < EPR && validR[lane])
                reds(&g_deg[eRowR[lane]], 1.0f);
        }
        barrow(row);  // protect EAP/XP/scalars before next tile's S0
        base = nbase;
    }
}

// ---------------------------------------------------------------- node finalize
__global__ __launch_bounds__(256) void post_kernel(
    const float* __restrict__ s, const float* __restrict__ v,
    const float* __restrict__ mgw2, const float* __restrict__ mgb2,
    const float* __restrict__ upw, const float* __restrict__ upb,
    const float* __restrict__ lng, const float* __restrict__ lnb,
    float* __restrict__ outs, float* __restrict__ outv, int N) {
    __shared__ float mw2t[64][132];
    __shared__ float upwt[64][68];
    __shared__ float zs[4][132];
    __shared__ float xs[4][68];
    __shared__ float sn[4][68];
    const int tid = threadIdx.x;
    for (int idx = tid; idx < 128 * 64; idx += 256) {
        int k = idx >> 6, f = idx & 63;
        mw2t[f][k] = mgw2[idx];
    }
    for (int idx = tid; idx < 64 * 64; idx += 256) {
        int k = idx >> 6, f = idx & 63;
        upwt[f][k] = upw[idx];
    }
    __syncthreads();
    const int slot = tid >> 6, f = tid & 63;
    for (int n0 = blockIdx.x * 4; n0 < N; n0 += gridDim.x * 4) {
        int n = n0 + slot;
        bool ok = (n < N);
        zs[slot][f]      = ok ? g_z[n * 128 + f] : 0.0f;
        zs[slot][64 + f] = ok ? g_z[n * 128 + 64 + f] : 0.0f;
        __syncthreads();
        float degv = ok ? g_deg[n] : 0.0f;
        float acc = degv * mgb2[f];
#pragma unroll 4
        for (int k = 0; k < 128; k += 4) {
            float4 w = *(const float4*)&mw2t[f][k];
            float4 x = *(const float4*)&zs[slot][k];
            acc += w.x * x.x + w.y * x.y + w.z * x.z + w.w * x.w;
        }
        xs[slot][f] = siluf(acc);
        __syncthreads();
        float acc2 = upb[f];
#pragma unroll 4
        for (int k = 0; k < 64; k += 4) {
            float4 w = *(const float4*)&upwt[f][k];
            float4 x = *(const float4*)&xs[slot][k];
            acc2 += w.x * x.x + w.y * x.y + w.z * x.z + w.w * x.w;
        }
        float snew = ok ? (s[n * 64 + f] + acc2) : 0.0f;
        sn[slot][f] = snew;
        __syncthreads();
        float sum = 0.0f, sq = 0.0f;
#pragma unroll 4
        for (int k = 0; k < 64; k += 4) {
            float4 t = *(const float4*)&sn[slot][k];
            sum += t.x + t.y + t.z + t.w;
            sq += t.x * t.x + t.y * t.y + t.z * t.z + t.w * t.w;
        }
        float mu = sum * (1.0f / 64.0f);
        float var = sq * (1.0f / 64.0f) - mu * mu;
        if (ok) {
            outs[n * 64 + f] = (snew - mu) * rsqrtf(var + 1e-5f) * lng[f] + lnb[f];
            if (f < 3) {
                float v0 = v[n * 3 + 0] + g_vagg[n * 3 + 0];
                float v1 = v[n * 3 + 1] + g_vagg[n * 3 + 1];
                float v2 = v[n * 3 + 2] + g_vagg[n * 3 + 2];
                float nrm = sqrtf(v0 * v0 + v1 * v1 + v2 * v2);
                float inv = 1.0f / fmaxf(nrm, 1e-6f);
                float val = (f == 0) ? v0 : (f == 1) ? v1 : v2;
                outv[n * 3 + f] = val * inv;
            }
        }
        __syncthreads();
    }
}

// ---------------------------------------------------------------- launch
extern "C" void kernel_launch(void* const* d_in, const int* in_sizes, int n_in,
                              void* d_out, int out_size) {
    const float* s    = (const float*)d_in[0];
    const float* v    = (const float*)d_in[1];
    const int*   ei   = (const int*)d_in[2];
    const float* ea   = (const float*)d_in[3];
    const float* evu  = (const float*)d_in[4];
    const float* ngw1 = (const float*)d_in[5];
    const float* ngb1 = (const float*)d_in[6];
    const float* ngw2 = (const float*)d_in[7];
    const float* ngb2 = (const float*)d_in[8];
    const float* egw1 = (const float*)d_in[9];
    const float* egb1 = (const float*)d_in[10];
    const float* egw2 = (const float*)d_in[11];
    const float* egb2 = (const float*)d_in[12];
    const float* mgw1 = (const float*)d_in[13];
    const float* mgb1 = (const float*)d_in[14];
    const float* mgw2 = (const float*)d_in[15];
    const float* mgb2 = (const float*)d_in[16];
    const float* pew  = (const float*)d_in[17];
    const float* peb  = (const float*)d_in[18];
    const float* upw  = (const float*)d_in[19];
    const float* upb  = (const float*)d_in[20];
    const float* lng  = (const float*)d_in[21];
    const float* lnb  = (const float*)d_in[22];

    const int N = in_sizes[0] / 64;
    const int E = in_sizes[2] / 2;

    float* outs = (float*)d_out;
    float* outv = outs + (size_t)N * 64;

    int nsm = 148;
    cudaDeviceGetAttribute(&nsm, cudaDevAttrMultiProcessorCount, 0);

    zero_kernel<<<512, 256>>>(N * 128, N * 3, N);
    pre_kernel<<<1184, 256>>>(s, ngw1, N);
    preW_kernel<<<128, 256>>>(ngw2, ngb2, egw2, egb2, mgw1, mgb1, mgw2, mgb2, pew, peb);

    cudaFuncSetAttribute(edge_kernel, cudaFuncAttributeMaxDynamicSharedMemorySize,
                         (int)sizeof(EdgeSmem));
    edge_kernel<<<nsm, 512, sizeof(EdgeSmem)>>>(
        v, ei, ea, evu, ngw1, ngb1, egw1, egb1, N, E);

    post_kernel<<<1184, 256>>>(s, v, mgw2, mgb2, upw, upb, lng, lnb, outs, outv, N);
}

// round 6
// speedup vs baseline: 1.0015x; 1.0015x over previous
#include <cuda_runtime.h>
#include <math.h>

#define MAXN 50000
#define MAXE 800000

// ---- device scratch (allocation-free rule) ----
__device__ float g_P[MAXN * 64];      // s @ ng_w1[0:64]
__device__ float g_z[MAXN * 128];     // segsum(silu(hm))
__device__ float g_vagg[MAXN * 3];
__device__ float g_deg[MAXN];
__device__ float g_Wpt[128 * 192];    // fused W' transposed: [o][r]
__device__ float g_b1p[128];          // fused bias into hm
__device__ float g_q[128];            // mg_w2 @ pe_w
__device__ float g_qb[1];             // b_mg2 @ pe_w + pe_b

__device__ __forceinline__ float siluf(float x) { return x / (1.0f + __expf(-x)); }

__device__ __forceinline__ void reds(float* p, float v) {
    asm volatile("red.global.add.f32 [%0], %1;" :: "l"(p), "f"(v) : "memory");
}
__device__ __forceinline__ void barrow(int id) {
    asm volatile("bar.sync %0, 64;" :: "r"(id) : "memory");
}

// ---- packed f32x2 helpers (Blackwell) ----
typedef unsigned long long u64t;
__device__ __forceinline__ u64t pack2(float x, float y) {
    u64t r; asm("mov.b64 %0, {%1,%2};" : "=l"(r) : "f"(x), "f"(y)); return r;
}
__device__ __forceinline__ float2 unpack2(u64t v) {
    float2 r; asm("mov.b64 {%0,%1}, %2;" : "=f"(r.x), "=f"(r.y) : "l"(v)); return r;
}
__device__ __forceinline__ void ffma2(u64t& d, u64t a, u64t b) {
    asm("fma.rn.f32x2 %0, %1, %2, %0;" : "+l"(d) : "l"(a), "l"(b));
}

// ---------------------------------------------------------------- zero scratch
__global__ void zero_kernel(int n128, int n3, int n1) {
    int i = blockIdx.x * blockDim.x + threadIdx.x;
    int stride = gridDim.x * blockDim.x;
    for (int k = i; k < n128; k += stride) g_z[k] = 0.0f;
    for (int k = i; k < n3; k += stride) g_vagg[k] = 0.0f;
    for (int k = i; k < n1; k += stride) g_deg[k] = 0.0f;
}

// ---------------------------------------------------------------- P = s @ ng_w1[0:64,:]
__global__ __launch_bounds__(256) void pre_kernel(const float* __restrict__ s,
                                                  const float* __restrict__ ngw1, int N) {
    __shared__ float wt[64][68];
    __shared__ float xs[4][68];
    const int tid = threadIdx.x;
    for (int idx = tid; idx < 64 * 64; idx += 256) {
        int k = idx >> 6, f = idx & 63;
        wt[f][k] = ngw1[idx];
    }
    __syncthreads();
    const int slot = tid >> 6, f = tid & 63;
    for (int n0 = blockIdx.x * 4; n0 < N; n0 += gridDim.x * 4) {
        int n = n0 + slot;
        xs[slot][f] = (n < N) ? s[n * 64 + f] : 0.0f;
        __syncthreads();
        float acc = 0.0f;
#pragma unroll 4
        for (int k = 0; k < 64; k += 4) {
            float4 w = *(const float4*)&wt[f][k];
            float4 x = *(const float4*)&xs[slot][k];
            acc += w.x * x.x + w.y * x.y + w.z * x.z + w.w * x.w;
        }
        if (n < N) g_P[n * 64 + f] = acc;
        __syncthreads();
    }
}

// ---------------------------------------------------------------- fold weights
__global__ void preW_kernel(const float* __restrict__ ngw2, const float* __restrict__ ngb2,
                            const float* __restrict__ egw2, const float* __restrict__ egb2,
                            const float* __restrict__ mgw1, const float* __restrict__ mgb1,
                            const float* __restrict__ mgw2, const float* __restrict__ mgb2,
                            const float* __restrict__ pew, const float* __restrict__ peb) {
    int idx = blockIdx.x * blockDim.x + threadIdx.x;
    int stride = gridDim.x * blockDim.x;
    for (int t = idx; t < 128 * 192 + 128 + 128 + 1; t += stride) {
        if (t < 128 * 192) {
            int o = t / 192, r = t % 192;
            int seg = r >> 6, rr = r & 63, koff = seg * 64;
            const float* src = (seg < 2) ? ngw2 : egw2;
            float val = 0.0f;
            for (int k = 0; k < 64; k++)
                val += src[rr * 64 + k] * mgw1[(koff + k) * 128 + o];
            g_Wpt[o * 192 + r] = val;
        } else if (t < 128 * 192 + 128) {
            int o = t - 128 * 192;
            float val = mgb1[o];
            for (int k = 0; k < 64; k++) {
                val += ngb2[k] * (mgw1[k * 128 + o] + mgw1[(64 + k) * 128 + o]);
                val += egb2[k] * mgw1[(128 + k) * 128 + o];
            }
            g_b1p[o] = val;
        } else if (t < 128 * 192 + 256) {
            int o = t - 128 * 192 - 128;
            float val = 0.0f;
            for (int j = 0; j < 64; j++) val += mgw2[o * 64 + j] * pew[j];
            g_q[o] = val;
        } else {
            float val = peb[0];
            for (int j = 0; j < 64; j++) val += mgb2[j] * pew[j];
            g_qb[0] = val;
        }
    }
}

// ---------------------------------------------------------------- fused edge kernel
// 512 threads = 8 independent rows x 64 lanes; each row owns 12 edges/tile (6 pairs).
// Cross-tile software prefetch hides LDG latency behind the S2 GEMM.
#define ROWS 8
#define EPR 12
#define NPAIR 6

struct __align__(16) EdgeSmem {
    float egw1t[64][68];               // eg_w1 transposed [f][k], k=0..64
    float wpt[128][196];               // fused W' transposed [o][r]
    float XP[ROWS][NPAIR][192][2];     // pair-interleaved X
    float EAP[ROWS][NPAIR][66][2];     // pair-interleaved edge_attr (+cross at k=64)
    float w65[64], bng1[64], beg1[64];
    float b1p[128], q[128];
    float resI[ROWS][EPR], resJ[ROWS][EPR];
    float evu_s[ROWS][EPR][3];
    int eRow[ROWS][EPR], eCol[ROWS][EPR], valid[ROWS][EPR];
    float qb;
};

__global__ __launch_bounds__(512) void edge_kernel(
    const float* __restrict__ v, const int* __restrict__ ei,
    const float* __restrict__ ea, const float* __restrict__ evu,
    const float* __restrict__ ngw1, const float* __restrict__ ngb1,
    const float* __restrict__ egw1, const float* __restrict__ egb1,
    int N, int E) {
    extern __shared__ char smem_raw[];
    EdgeSmem& sm = *reinterpret_cast<EdgeSmem*>(smem_raw);
    const int tid = threadIdx.x;

    // ---- one-time staging ----
    for (int idx = tid; idx < 65 * 64; idx += 512) {
        int k = idx >> 6, f = idx & 63;
        sm.egw1t[f][k] = egw1[idx];
    }
    for (int idx = tid; idx < 128 * 192; idx += 512) {
        int o = idx / 192, r = idx % 192;
        sm.wpt[o][r] = g_Wpt[idx];
    }
    if (tid < 64) {
        sm.w65[tid] = ngw1[64 * 64 + tid];
        sm.bng1[tid] = ngb1[tid];
        sm.beg1[tid] = egb1[tid];
    } else if (tid < 192) {
        sm.b1p[tid - 64] = g_b1p[tid - 64];
    } else if (tid < 320) {
        sm.q[tid - 192] = g_q[tid - 192];
    } else if (tid == 320) {
        sm.qb = g_qb[0];
    }
    __syncthreads();

    const int f = tid & 63;
    const int row = tid >> 6;        // 0..7
    const int lane = tid & 31;
    const int half = (tid >> 5) & 1;
    const float qbh = 0.5f * sm.qb;
    const int stride = gridDim.x * (ROWS * EPR);

    // hoisted per-lane constants / pointers
    const float begf = sm.beg1[f];
    const float w64v = sm.egw1t[f][64];
    const float w65v = sm.w65[f], b1v = sm.bng1[f];
    const float bA = sm.b1p[f], bB = sm.b1p[64 + f];
    const float qf = sm.q[f], qg = sm.q[64 + f];
    const float* egrow = sm.egw1t[f];
    const float* warow = sm.wpt[f];
    const float* wbrow = sm.wpt[64 + f];
    float (*XPr)[192][2] = sm.XP[row];
    float (*EAPr)[66][2] = sm.EAP[row];
    int* eRowR = sm.eRow[row];
    int* eColR = sm.eCol[row];
    int* validR = sm.valid[row];

    // ---- prefetch registers (consumed at next S0) ----
    float pfa[12];                       // 3 x (a0.x, a1.x, a0.y, a1.y)
    int pfr = 0, pfc = 0, pfok = 0;
    float pfu0 = 0.f, pfu1 = 0.f, pfu2 = 0.f;
    float pvi0 = 0.f, pvi1 = 0.f, pvi2 = 0.f;
    float pvj0 = 0.f, pvj1 = 0.f, pvj2 = 0.f;

    int base = blockIdx.x * (ROWS * EPR) + row * EPR;

    // ---- cold prefetch for first tile ----
    if (f < EPR) {
        int e = base + f;
        pfok = (e < E);
        if (pfok) {
            pfr = ei[e]; pfc = ei[E + e];
            pfu0 = evu[e * 3 + 0]; pfu1 = evu[e * 3 + 1]; pfu2 = evu[e * 3 + 2];
            pvi0 = v[pfr * 3 + 0]; pvi1 = v[pfr * 3 + 1]; pvi2 = v[pfr * 3 + 2];
            pvj0 = v[pfc * 3 + 0]; pvj1 = v[pfc * 3 + 1]; pvj2 = v[pfc * 3 + 2];
        }
    }
#pragma unroll
    for (int it = 0; it < 3; it++) {
        int idx = f + 64 * it;
        int p = idx >> 5, kk = (idx & 31) * 2;
        int e0 = base + 2 * p, e1 = e0 + 1;
        float2 a0 = make_float2(0.f, 0.f), a1 = a0;
        if (e0 < E) a0 = *(const float2*)&ea[(size_t)e0 * 64 + kk];
        if (e1 < E) a1 = *(const float2*)&ea[(size_t)e1 * 64 + kk];
        pfa[it * 4 + 0] = a0.x; pfa[it * 4 + 1] = a1.x;
        pfa[it * 4 + 2] = a0.y; pfa[it * 4 + 3] = a1.y;
    }

    for (; base < E; ) {
        // ---- S0: consume prefetched data into smem ----
        if (f < EPR) {
            validR[f] = pfok;
            if (pfok) {
                eRowR[f] = pfr; eColR[f] = pfc;
                sm.evu_s[row][f][0] = pfu0; sm.evu_s[row][f][1] = pfu1; sm.evu_s[row][f][2] = pfu2;
                sm.resI[row][f] = 1.0f - (pvi0 * pfu0 + pvi1 * pfu1 + pvi2 * pfu2);
                sm.resJ[row][f] = 1.0f + (pvj0 * pfu0 + pvj1 * pfu1 + pvj2 * pfu2);
                float cx = pvi1 * pvj2 - pvi2 * pvj1;
                float cy = pvi2 * pvj0 - pvi0 * pvj2;
                float cz = pvi0 * pvj1 - pvi1 * pvj0;
                EAPr[f >> 1][64][f & 1] = sqrtf(cx * cx + cy * cy + cz * cz);
            } else {
                eRowR[f] = 0; eColR[f] = 0;
                sm.resI[row][f] = 0.0f; sm.resJ[row][f] = 0.0f;
                EAPr[f >> 1][64][f & 1] = 0.0f;
                sm.evu_s[row][f][0] = sm.evu_s[row][f][1] = sm.evu_s[row][f][2] = 0.0f;
            }
        }
#pragma unroll
        for (int it = 0; it < 3; it++) {
            int idx = f + 64 * it;
            int p = idx >> 5, kk = (idx & 31) * 2;
            *(float4*)&EAPr[p][kk][0] =
                make_float4(pfa[it * 4 + 0], pfa[it * 4 + 1], pfa[it * 4 + 2], pfa[it * 4 + 3]);
        }

        const int nbase = base + stride;
        // ---- prefetch stage 1: ei + evu for next tile (flies during S1) ----
        if (f < EPR) {
            int e = nbase + f;
            pfok = (e < E);
            if (pfok) {
                pfr = ei[e]; pfc = ei[E + e];
                pfu0 = evu[e * 3 + 0]; pfu1 = evu[e * 3 + 1]; pfu2 = evu[e * 3 + 2];
            } else { pfr = 0; pfc = 0; pfu0 = pfu1 = pfu2 = 0.f; }
        }
        barrow(row);

        // ---- S1: h_e (packed GEMM), h_i/h_j via P ----
        {
            u64t aE[NPAIR];
            u64t binit = pack2(begf, begf);
#pragma unroll
            for (int p = 0; p < NPAIR; p++) aE[p] = binit;
#pragma unroll 4
            for (int k = 0; k < 64; k += 4) {
                float4 w = *(const float4*)&egrow[k];
                u64t w0 = pack2(w.x, w.x), w1 = pack2(w.y, w.y);
                u64t w2 = pack2(w.z, w.z), w3 = pack2(w.w, w.w);
#pragma unroll
                for (int p = 0; p < NPAIR; p++) {
                    ulonglong2 q0 = *(const ulonglong2*)&EAPr[p][k][0];
                    ulonglong2 q1 = *(const ulonglong2*)&EAPr[p][k + 2][0];
                    ffma2(aE[p], q0.x, w0);
                    ffma2(aE[p], q0.y, w1);
                    ffma2(aE[p], q1.x, w2);
                    ffma2(aE[p], q1.y, w3);
                }
            }
            u64t wc = pack2(w64v, w64v);
#pragma unroll
            for (int p = 0; p < NPAIR; p++) {
                u64t cr = *(const u64t*)&EAPr[p][64][0];
                ffma2(aE[p], cr, wc);
                float2 g = unpack2(aE[p]);
                float2 o; o.x = siluf(g.x); o.y = siluf(g.y);
                *(float2*)&XPr[p][128 + f][0] = o;
            }
        }
#pragma unroll
        for (int p = 0; p < NPAIR; p++) {
            int j0 = 2 * p, j1 = 2 * p + 1;
            float pi0 = 0.f, pi1 = 0.f, pj0 = 0.f, pj1 = 0.f;
            if (validR[j0]) { pi0 = g_P[eRowR[j0] * 64 + f]; pj0 = g_P[eColR[j0] * 64 + f]; }
            if (validR[j1]) { pi1 = g_P[eRowR[j1] * 64 + f]; pj1 = g_P[eColR[j1] * 64 + f]; }
            float2 hi, hj;
            hi.x = siluf(pi0 + sm.resI[row][j0] * w65v + b1v);
            hi.y = siluf(pi1 + sm.resI[row][j1] * w65v + b1v);
            hj.x = siluf(pj0 + sm.resJ[row][j0] * w65v + b1v);
            hj.y = siluf(pj1 + sm.resJ[row][j1] * w65v + b1v);
            *(float2*)&XPr[p][f][0] = hi;
            *(float2*)&XPr[p][64 + f][0] = hj;
        }
        barrow(row);

        // ---- prefetch stage 2: ea + v gathers for next tile (fly during S2) ----
#pragma unroll
        for (int it = 0; it < 3; it++) {
            int idx = f + 64 * it;
            int p = idx >> 5, kk = (idx & 31) * 2;
            int e0 = nbase + 2 * p, e1 = e0 + 1;
            float2 a0 = make_float2(0.f, 0.f), a1 = a0;
            if (e0 < E) a0 = *(const float2*)&ea[(size_t)e0 * 64 + kk];
            if (e1 < E) a1 = *(const float2*)&ea[(size_t)e1 * 64 + kk];
            pfa[it * 4 + 0] = a0.x; pfa[it * 4 + 1] = a1.x;
            pfa[it * 4 + 2] = a0.y; pfa[it * 4 + 3] = a1.y;
        }
        if (f < EPR && pfok) {
            pvi0 = v[pfr * 3 + 0]; pvi1 = v[pfr * 3 + 1]; pvi2 = v[pfr * 3 + 2];
            pvj0 = v[pfc * 3 + 0]; pvj1 = v[pfc * 3 + 1]; pvj2 = v[pfc * 3 + 2];
        }

        // ---- S2: hm = X @ W' + b1p (packed) ; g = silu ; RED g_z ; coeff ----
        {
            u64t accA[NPAIR], accB[NPAIR];
            u64t ia = pack2(bA, bA), ib = pack2(bB, bB);
#pragma unroll
            for (int p = 0; p < NPAIR; p++) { accA[p] = ia; accB[p] = ib; }
#pragma unroll 4
            for (int k = 0; k < 192; k += 4) {
                float4 wa = *(const float4*)&warow[k];
                float4 wb = *(const float4*)&wbrow[k];
                u64t wa0 = pack2(wa.x, wa.x), wa1 = pack2(wa.y, wa.y);
                u64t wa2 = pack2(wa.z, wa.z), wa3 = pack2(wa.w, wa.w);
                u64t wb0 = pack2(wb.x, wb.x), wb1 = pack2(wb.y, wb.y);
                u64t wb2 = pack2(wb.z, wb.z), wb3 = pack2(wb.w, wb.w);
#pragma unroll
                for (int p = 0; p < NPAIR; p++) {
                    ulonglong2 q0 = *(const ulonglong2*)&XPr[p][k][0];
                    ulonglong2 q1 = *(const ulonglong2*)&XPr[p][k + 2][0];
                    ffma2(accA[p], q0.x, wa0);
                    ffma2(accB[p], q0.x, wb0);
                    ffma2(accA[p], q0.y, wa1);
                    ffma2(accB[p], q0.y, wb1);
                    ffma2(accA[p], q1.x, wa2);
                    ffma2(accB[p], q1.x, wb2);
                    ffma2(accA[p], q1.y, wa3);
                    ffma2(accB[p], q1.y, wb3);
                }
            }
            float pco[EPR];
#pragma unroll
            for (int p = 0; p < NPAIR; p++) {
                float2 gA = unpack2(accA[p]);
                float2 gB = unpack2(accB[p]);
                gA.x = siluf(gA.x); gA.y = siluf(gA.y);
                gB.x = siluf(gB.x); gB.y = siluf(gB.y);
                int j0 = 2 * p, j1 = 2 * p + 1;
                if (validR[j0]) {
                    int dst = eRowR[j0];
                    reds(&g_z[dst * 128 + f], gA.x);
                    reds(&g_z[dst * 128 + 64 + f], gB.x);
                }
                if (validR[j1]) {
                    int dst = eRowR[j1];
                    reds(&g_z[dst * 128 + f], gA.y);
                    reds(&g_z[dst * 128 + 64 + f], gB.y);
                }
                pco[j0] = gA.x * qf + gB.x * qg;
                pco[j1] = gA.y * qf + gB.y * qg;
            }
#pragma unroll
            for (int j = 0; j < EPR; j++) {
#pragma unroll
                for (int off = 16; off > 0; off >>= 1)
                    pco[j] += __shfl_xor_sync(0xffffffffu, pco[j], off);
            }
            // each warp REDs qb/2 + its half-sum for every edge (3*EPR = 36 > 32 lanes)
            for (int t = lane; t < 3 * EPR; t += 32) {
                int j = t / 3, c = t % 3;
                if (validR[j]) {
                    float cf = qbh + pco[j];
                    reds(&g_vagg[eRowR[j] * 3 + c], sm.evu_s[row][j][c] * cf);
                }
            }
            if (half == 0 && lane < EPR && validR[lane])
                reds(&g_deg[eRowR[lane]], 1.0f);
        }
        barrow(row);  // protect EAP/XP/scalars before next tile's S0
        base = nbase;
    }
}

// ---------------------------------------------------------------- node finalize
__global__ __launch_bounds__(256) void post_kernel(
    const float* __restrict__ s, const float* __restrict__ v,
    const float* __restrict__ mgw2, const float* __restrict__ mgb2,
    const float* __restrict__ upw, const float* __restrict__ upb,
    const float* __restrict__ lng, const float* __restrict__ lnb,
    float* __restrict__ outs, float* __restrict__ outv, int N) {
    __shared__ float mw2t[64][132];
    __shared__ float upwt[64][68];
    __shared__ float zs[4][132];
    __shared__ float xs[4][68];
    __shared__ float sn[4][68];
    const int tid = threadIdx.x;
    for (int idx = tid; idx < 128 * 64; idx += 256) {
        int k = idx >> 6, f = idx & 63;
        mw2t[f][k] = mgw2[idx];
    }
    for (int idx = tid; idx < 64 * 64; idx += 256) {
        int k = idx >> 6, f = idx & 63;
        upwt[f][k] = upw[idx];
    }
    __syncthreads();
    const int slot = tid >> 6, f = tid & 63;
    for (int n0 = blockIdx.x * 4; n0 < N; n0 += gridDim.x * 4) {
        int n = n0 + slot;
        bool ok = (n < N);
        zs[slot][f]      = ok ? g_z[n * 128 + f] : 0.0f;
        zs[slot][64 + f] = ok ? g_z[n * 128 + 64 + f] : 0.0f;
        __syncthreads();
        float degv = ok ? g_deg[n] : 0.0f;
        float acc = degv * mgb2[f];
#pragma unroll 4
        for (int k = 0; k < 128; k += 4) {
            float4 w = *(const float4*)&mw2t[f][k];
            float4 x = *(const float4*)&zs[slot][k];
            acc += w.x * x.x + w.y * x.y + w.z * x.z + w.w * x.w;
        }
        xs[slot][f] = siluf(acc);
        __syncthreads();
        float acc2 = upb[f];
#pragma unroll 4
        for (int k = 0; k < 64; k += 4) {
            float4 w = *(const float4*)&upwt[f][k];
            float4 x = *(const float4*)&xs[slot][k];
            acc2 += w.x * x.x + w.y * x.y + w.z * x.z + w.w * x.w;
        }
        float snew = ok ? (s[n * 64 + f] + acc2) : 0.0f;
        sn[slot][f] = snew;
        __syncthreads();
        float sum = 0.0f, sq = 0.0f;
#pragma unroll 4
        for (int k = 0; k < 64; k += 4) {
            float4 t = *(const float4*)&sn[slot][k];
            sum += t.x + t.y + t.z + t.w;
            sq += t.x * t.x + t.y * t.y + t.z * t.z + t.w * t.w;
        }
        float mu = sum * (1.0f / 64.0f);
        float var = sq * (1.0f / 64.0f) - mu * mu;
        if (ok) {
            outs[n * 64 + f] = (snew - mu) * rsqrtf(var + 1e-5f) * lng[f] + lnb[f];
            if (f < 3) {
                float v0 = v[n * 3 + 0] + g_vagg[n * 3 + 0];
                float v1 = v[n * 3 + 1] + g_vagg[n * 3 + 1];
                float v2 = v[n * 3 + 2] + g_vagg[n * 3 + 2];
                float nrm = sqrtf(v0 * v0 + v1 * v1 + v2 * v2);
                float inv = 1.0f / fmaxf(nrm, 1e-6f);
                float val = (f == 0) ? v0 : (f == 1) ? v1 : v2;
                outv[n * 3 + f] = val * inv;
            }
        }
        __syncthreads();
    }
}

// ---------------------------------------------------------------- launch
extern "C" void kernel_launch(void* const* d_in, const int* in_sizes, int n_in,
                              void* d_out, int out_size) {
    const float* s    = (const float*)d_in[0];
    const float* v    = (const float*)d_in[1];
    const int*   ei   = (const int*)d_in[2];
    const float* ea   = (const float*)d_in[3];
    const float* evu  = (const float*)d_in[4];
    const float* ngw1 = (const float*)d_in[5];
    const float* ngb1 = (const float*)d_in[6];
    const float* ngw2 = (const float*)d_in[7];
    const float* ngb2 = (const float*)d_in[8];
    const float* egw1 = (const float*)d_in[9];
    const float* egb1 = (const float*)d_in[10];
    const float* egw2 = (const float*)d_in[11];
    const float* egb2 = (const float*)d_in[12];
    const float* mgw1 = (const float*)d_in[13];
    const float* mgb1 = (const float*)d_in[14];
    const float* mgw2 = (const float*)d_in[15];
    const float* mgb2 = (const float*)d_in[16];
    const float* pew  = (const float*)d_in[17];
    const float* peb  = (const float*)d_in[18];
    const float* upw  = (const float*)d_in[19];
    const float* upb  = (const float*)d_in[20];
    const float* lng  = (const float*)d_in[21];
    const float* lnb  = (const float*)d_in[22];

    const int N = in_sizes[0] / 64;
    const int E = in_sizes[2] / 2;

    float* outs = (float*)d_out;
    float* outv = outs + (size_t)N * 64;

    int nsm = 148;
    cudaDeviceGetAttribute(&nsm, cudaDevAttrMultiProcessorCount, 0);

    zero_kernel<<<512, 256>>>(N * 128, N * 3, N);
    pre_kernel<<<1184, 256>>>(s, ngw1, N);
    preW_kernel<<<128, 256>>>(ngw2, ngb2, egw2, egb2, mgw1, mgb1, mgw2, mgb2, pew, peb);

    cudaFuncSetAttribute(edge_kernel, cudaFuncAttributeMaxDynamicSharedMemorySize,
                         (int)sizeof(EdgeSmem));
    edge_kernel<<<nsm, 512, sizeof(EdgeSmem)>>>(
        v, ei, ea, evu, ngw1, ngb1, egw1, egb1, N, E);

    post_kernel<<<1184, 256>>>(s, v, mgw2, mgb2, upw, upb, lng, lnb, outs, outv, N);
}

// round 7
// speedup vs baseline: 1.0904x; 1.0888x over previous
#include <cuda_runtime.h>
#include <math.h>

#define MAXN 50000
#define MAXE 800000

// ---- device scratch (allocation-free rule) ----
__device__ float g_P[MAXN * 64];      // s @ ng_w1[0:64]
__device__ float g_z[MAXN * 128];     // segsum(silu(hm))
__device__ float g_vagg[MAXN * 3];
__device__ float g_deg[MAXN];
__device__ float g_Wpt[128 * 192];    // fused W' transposed: [o][r]
__device__ float g_b1p[128];          // fused bias into hm
__device__ float g_q[128];            // mg_w2 @ pe_w
__device__ float g_qb[1];             // b_mg2 @ pe_w + pe_b

__device__ __forceinline__ float siluf(float x) { return x / (1.0f + __expf(-x)); }

__device__ __forceinline__ void reds(float* p, float v) {
    asm volatile("red.global.add.f32 [%0], %1;" :: "l"(p), "f"(v) : "memory");
}

// ---- packed f32x2 helpers (Blackwell) ----
typedef unsigned long long u64t;
__device__ __forceinline__ u64t pack2(float x, float y) {
    u64t r; asm("mov.b64 %0, {%1,%2};" : "=l"(r) : "f"(x), "f"(y)); return r;
}
__device__ __forceinline__ float2 unpack2(u64t v) {
    float2 r; asm("mov.b64 {%0,%1}, %2;" : "=f"(r.x), "=f"(r.y) : "l"(v)); return r;
}
__device__ __forceinline__ void ffma2(u64t& d, u64t a, u64t b) {
    asm("fma.rn.f32x2 %0, %1, %2, %0;" : "+l"(d) : "l"(a), "l"(b));
}

// ---------------------------------------------------------------- zero scratch
__global__ void zero_kernel(int n128, int n3, int n1) {
    int i = blockIdx.x * blockDim.x + threadIdx.x;
    int stride = gridDim.x * blockDim.x;
    for (int k = i; k < n128; k += stride) g_z[k] = 0.0f;
    for (int k = i; k < n3; k += stride) g_vagg[k] = 0.0f;
    for (int k = i; k < n1; k += stride) g_deg[k] = 0.0f;
}

// ---------------------------------------------------------------- P = s @ ng_w1[0:64,:]
__global__ __launch_bounds__(256) void pre_kernel(const float* __restrict__ s,
                                                  const float* __restrict__ ngw1, int N) {
    __shared__ float wt[64][68];
    __shared__ float xs[4][68];
    const int tid = threadIdx.x;
    for (int idx = tid; idx < 64 * 64; idx += 256) {
        int k = idx >> 6, f = idx & 63;
        wt[f][k] = ngw1[idx];
    }
    __syncthreads();
    const int slot = tid >> 6, f = tid & 63;
    for (int n0 = blockIdx.x * 4; n0 < N; n0 += gridDim.x * 4) {
        int n = n0 + slot;
        xs[slot][f] = (n < N) ? s[n * 64 + f] : 0.0f;
        __syncthreads();
        float acc = 0.0f;
#pragma unroll 4
        for (int k = 0; k < 64; k += 4) {
            float4 w = *(const float4*)&wt[f][k];
            float4 x = *(const float4*)&xs[slot][k];
            acc += w.x * x.x + w.y * x.y + w.z * x.z + w.w * x.w;
        }
        if (n < N) g_P[n * 64 + f] = acc;
        __syncthreads();
    }
}

// ---------------------------------------------------------------- fold weights
__global__ void preW_kernel(const float* __restrict__ ngw2, const float* __restrict__ ngb2,
                            const float* __restrict__ egw2, const float* __restrict__ egb2,
                            const float* __restrict__ mgw1, const float* __restrict__ mgb1,
                            const float* __restrict__ mgw2, const float* __restrict__ mgb2,
                            const float* __restrict__ pew, const float* __restrict__ peb) {
    int idx = blockIdx.x * blockDim.x + threadIdx.x;
    int stride = gridDim.x * blockDim.x;
    for (int t = idx; t < 128 * 192 + 128 + 128 + 1; t += stride) {
        if (t < 128 * 192) {
            int o = t / 192, r = t % 192;
            int seg = r >> 6, rr = r & 63, koff = seg * 64;
            const float* src = (seg < 2) ? ngw2 : egw2;
            float val = 0.0f;
            for (int k = 0; k < 64; k++)
                val += src[rr * 64 + k] * mgw1[(koff + k) * 128 + o];
            g_Wpt[o * 192 + r] = val;
        } else if (t < 128 * 192 + 128) {
            int o = t - 128 * 192;
            float val = mgb1[o];
            for (int k = 0; k < 64; k++) {
                val += ngb2[k] * (mgw1[k * 128 + o] + mgw1[(64 + k) * 128 + o]);
                val += egb2[k] * mgw1[(128 + k) * 128 + o];
            }
            g_b1p[o] = val;
        } else if (t < 128 * 192 + 256) {
            int o = t - 128 * 192 - 128;
            float val = 0.0f;
            for (int j = 0; j < 64; j++) val += mgw2[o * 64 + j] * pew[j];
            g_q[o] = val;
        } else {
            float val = peb[0];
            for (int j = 0; j < 64; j++) val += mgb2[j] * pew[j];
            g_qb[0] = val;
        }
    }
}

// ---------------------------------------------------------------- fused edge kernel
// 512 threads = 16 fully independent warps; each warp owns 8 edges/tile (4 pairs).
// Tf=4 register blocking: lane computes output rows L, L+32, L+64, L+96 (f32x2 over
// the edge pair). No block/named barriers in the main loop — __syncwarp only.
#define WPB 16
#define NPAIR 4
#define EPW 8

struct __align__(16) EdgeSmem {
    float wpt[128][196];            // fused W' transposed [o][k]
    float egw1t[64][68];            // eg_w1 transposed [f][k], k=0..64
    float XP[WPB][NPAIR][192][2];   // pair-interleaved X; k<66 doubles as ea staging
    float w65[64], bng1[64], beg1[64];
    float b1p[128], q[128];
    float resI[WPB][EPW], resJ[WPB][EPW];
    float evu_s[WPB][EPW][3];
    int eRow[WPB][EPW], eCol[WPB][EPW], valid[WPB][EPW];
    float qb;
};

__global__ __launch_bounds__(512) void edge_kernel(
    const float* __restrict__ v, const int* __restrict__ ei,
    const float* __restrict__ ea, const float* __restrict__ evu,
    const float* __restrict__ ngw1, const float* __restrict__ ngb1,
    const float* __restrict__ egw1, const float* __restrict__ egb1,
    int N, int E) {
    extern __shared__ char smem_raw[];
    EdgeSmem& sm = *reinterpret_cast<EdgeSmem*>(smem_raw);
    const int tid = threadIdx.x;

    // ---- one-time staging ----
    for (int idx = tid; idx < 65 * 64; idx += 512) {
        int k = idx >> 6, f = idx & 63;
        sm.egw1t[f][k] = egw1[idx];
    }
    for (int idx = tid; idx < 128 * 192; idx += 512) {
        int o = idx / 192, r = idx % 192;
        sm.wpt[o][r] = g_Wpt[idx];
    }
    if (tid < 64) {
        sm.w65[tid] = ngw1[64 * 64 + tid];
        sm.bng1[tid] = ngb1[tid];
        sm.beg1[tid] = egb1[tid];
    } else if (tid < 192) {
        sm.b1p[tid - 64] = g_b1p[tid - 64];
    } else if (tid < 320) {
        sm.q[tid - 192] = g_q[tid - 192];
    } else if (tid == 320) {
        sm.qb = g_qb[0];
    }
    __syncthreads();

    const int lane = tid & 31;
    const int w = tid >> 5;
    const int L = lane;

    // hoisted per-lane constants / row pointers
    const float* wpt0 = sm.wpt[L];
    const float* wpt1 = sm.wpt[L + 32];
    const float* wpt2 = sm.wpt[L + 64];
    const float* wpt3 = sm.wpt[L + 96];
    const float* eg0 = sm.egw1t[L];
    const float* eg1 = sm.egw1t[L + 32];
    const float be0 = sm.beg1[L], be1 = sm.beg1[L + 32];
    const float eg0c = eg0[64], eg1c = eg1[64];
    const float w650 = sm.w65[L], w651 = sm.w65[L + 32];
    const float bn0 = sm.bng1[L], bn1 = sm.bng1[L + 32];
    const float b1p0 = sm.b1p[L], b1p1 = sm.b1p[L + 32];
    const float b1p2 = sm.b1p[L + 64], b1p3 = sm.b1p[L + 96];
    const float q0v = sm.q[L], q1v = sm.q[L + 32];
    const float q2v = sm.q[L + 64], q3v = sm.q[L + 96];
    const float qb = sm.qb;
    float (*XPw)[192][2] = sm.XP[w];
    int* eRowW = sm.eRow[w];
    int* eColW = sm.eCol[w];
    int* validW = sm.valid[w];
    float* resIW = sm.resI[w];
    float* resJW = sm.resJ[w];

    int base = (blockIdx.x * WPB + w) * EPW;
    const int stride = gridDim.x * (WPB * EPW);

    for (; base < E; base += stride) {
        // ---- S0: metadata (lanes 0..7) + ea staging into XP k<64 ----
        if (lane < EPW) {
            int e = base + lane;
            int ok = (e < E);
            validW[lane] = ok;
            if (ok) {
                int r = ei[e], c = ei[E + e];
                eRowW[lane] = r; eColW[lane] = c;
                float vx = v[r * 3 + 0], vy = v[r * 3 + 1], vz = v[r * 3 + 2];
                float wx = v[c * 3 + 0], wy = v[c * 3 + 1], wz = v[c * 3 + 2];
                float ux = evu[e * 3 + 0], uy = evu[e * 3 + 1], uz = evu[e * 3 + 2];
                sm.evu_s[w][lane][0] = ux; sm.evu_s[w][lane][1] = uy; sm.evu_s[w][lane][2] = uz;
                resIW[lane] = 1.0f - (vx * ux + vy * uy + vz * uz);
                resJW[lane] = 1.0f + (wx * ux + wy * uy + wz * uz);
                float cx = vy * wz - vz * wy;
                float cy = vz * wx - vx * wz;
                float cz = vx * wy - vy * wx;
                XPw[lane >> 1][64][lane & 1] = sqrtf(cx * cx + cy * cy + cz * cz);
            } else {
                eRowW[lane] = 0; eColW[lane] = 0;
                resIW[lane] = 0.0f; resJW[lane] = 0.0f;
                sm.evu_s[w][lane][0] = sm.evu_s[w][lane][1] = sm.evu_s[w][lane][2] = 0.0f;
                XPw[lane >> 1][64][lane & 1] = 0.0f;
            }
        }
#pragma unroll
        for (int it = 0; it < 4; it++) {
            int idx = lane + 32 * it;
            int p = idx >> 5, kk = (idx & 31) * 2;
            int e0 = base + 2 * p, e1 = e0 + 1;
            float2 a0 = make_float2(0.f, 0.f), a1 = a0;
            if (e0 < E) a0 = *(const float2*)&ea[(size_t)e0 * 64 + kk];
            if (e1 < E) a1 = *(const float2*)&ea[(size_t)e1 * 64 + kk];
            *(float4*)&XPw[p][kk][0] = make_float4(a0.x, a1.x, a0.y, a1.y);
        }
        __syncwarp();

        // ---- S1a: h_e GEMM (reads ea region of XP) ----
        u64t hE0[NPAIR], hE1[NPAIR];
        {
            u64t i0 = pack2(be0, be0), i1 = pack2(be1, be1);
#pragma unroll
            for (int p = 0; p < NPAIR; p++) { hE0[p] = i0; hE1[p] = i1; }
        }
#pragma unroll 8
        for (int k = 0; k < 64; k += 2) {
            float2 wA = *(const float2*)&eg0[k];
            float2 wB = *(const float2*)&eg1[k];
            u64t A0 = pack2(wA.x, wA.x), A1 = pack2(wA.y, wA.y);
            u64t B0 = pack2(wB.x, wB.x), B1 = pack2(wB.y, wB.y);
#pragma unroll
            for (int p = 0; p < NPAIR; p++) {
                ulonglong2 xq = *(const ulonglong2*)&XPw[p][k][0];
                ffma2(hE0[p], xq.x, A0);
                ffma2(hE1[p], xq.x, B0);
                ffma2(hE0[p], xq.y, A1);
                ffma2(hE1[p], xq.y, B1);
            }
        }
        {
            u64t C0 = pack2(eg0c, eg0c), C1 = pack2(eg1c, eg1c);
#pragma unroll
            for (int p = 0; p < NPAIR; p++) {
                u64t cr = *(const u64t*)&XPw[p][64][0];
                ffma2(hE0[p], cr, C0);
                ffma2(hE1[p], cr, C1);
            }
        }

        // ---- S1b: h_i / h_j into registers (gathers overlap the GEMM above) ----
        u64t hi0[NPAIR], hi1[NPAIR], hj0[NPAIR], hj1[NPAIR];
#pragma unroll
        for (int p = 0; p < NPAIR; p++) {
            int j0 = 2 * p, j1 = 2 * p + 1;
            float a0 = 0.f, b0 = 0.f, c0 = 0.f, d0 = 0.f;
            float a1 = 0.f, b1 = 0.f, c1 = 0.f, d1 = 0.f;
            if (validW[j0]) {
                int r = eRowW[j0], c = eColW[j0];
                a0 = g_P[r * 64 + L];  b0 = g_P[r * 64 + L + 32];
                c0 = g_P[c * 64 + L];  d0 = g_P[c * 64 + L + 32];
            }
            if (validW[j1]) {
                int r = eRowW[j1], c = eColW[j1];
                a1 = g_P[r * 64 + L];  b1 = g_P[r * 64 + L + 32];
                c1 = g_P[c * 64 + L];  d1 = g_P[c * 64 + L + 32];
            }
            float rI0 = resIW[j0], rI1 = resIW[j1];
            float rJ0 = resJW[j0], rJ1 = resJW[j1];
            hi0[p] = pack2(siluf(a0 + rI0 * w650 + bn0), siluf(a1 + rI1 * w650 + bn0));
            hi1[p] = pack2(siluf(b0 + rI0 * w651 + bn1), siluf(b1 + rI1 * w651 + bn1));
            hj0[p] = pack2(siluf(c0 + rJ0 * w650 + bn0), siluf(c1 + rJ1 * w650 + bn0));
            hj1[p] = pack2(siluf(d0 + rJ0 * w651 + bn1), siluf(d1 + rJ1 * w651 + bn1));
        }
        __syncwarp();  // ea region reads done -> safe to overwrite with h_i/h_j

        // ---- stores: build full X ----
#pragma unroll
        for (int p = 0; p < NPAIR; p++) {
            *(u64t*)&XPw[p][L][0] = hi0[p];
            *(u64t*)&XPw[p][L + 32][0] = hi1[p];
            *(u64t*)&XPw[p][64 + L][0] = hj0[p];
            *(u64t*)&XPw[p][64 + L + 32][0] = hj1[p];
            float2 t0 = unpack2(hE0[p]);
            float2 t1 = unpack2(hE1[p]);
            *(u64t*)&XPw[p][128 + L][0] = pack2(siluf(t0.x), siluf(t0.y));
            *(u64t*)&XPw[p][128 + L + 32][0] = pack2(siluf(t1.x), siluf(t1.y));
        }
        __syncwarp();

        // ---- S2: hm = X @ W' + b1p, Tf=4 register blocking ----
        u64t ac0[NPAIR], ac1[NPAIR], ac2[NPAIR], ac3[NPAIR];
        {
            u64t i0 = pack2(b1p0, b1p0), i1 = pack2(b1p1, b1p1);
            u64t i2 = pack2(b1p2, b1p2), i3 = pack2(b1p3, b1p3);
#pragma unroll
            for (int p = 0; p < NPAIR; p++) { ac0[p] = i0; ac1[p] = i1; ac2[p] = i2; ac3[p] = i3; }
        }
#pragma unroll 8
        for (int k = 0; k < 192; k += 2) {
            float2 w0 = *(const float2*)&wpt0[k];
            float2 w1 = *(const float2*)&wpt1[k];
            float2 w2 = *(const float2*)&wpt2[k];
            float2 w3 = *(const float2*)&wpt3[k];
            u64t W00 = pack2(w0.x, w0.x), W01 = pack2(w0.y, w0.y);
            u64t W10 = pack2(w1.x, w1.x), W11 = pack2(w1.y, w1.y);
            u64t W20 = pack2(w2.x, w2.x), W21 = pack2(w2.y, w2.y);
            u64t W30 = pack2(w3.x, w3.x), W31 = pack2(w3.y, w3.y);
#pragma unroll
            for (int p = 0; p < NPAIR; p++) {
                ulonglong2 xq = *(const ulonglong2*)&XPw[p][k][0];
                ffma2(ac0[p], xq.x, W00);
                ffma2(ac1[p], xq.x, W10);
                ffma2(ac2[p], xq.x, W20);
                ffma2(ac3[p], xq.x, W30);
                ffma2(ac0[p], xq.y, W01);
                ffma2(ac1[p], xq.y, W11);
                ffma2(ac2[p], xq.y, W21);
                ffma2(ac3[p], xq.y, W31);
            }
        }

        // ---- epilogue: silu, RED g_z, coeff, RED v_agg/deg ----
        float pco[EPW];
#pragma unroll
        for (int p = 0; p < NPAIR; p++) {
            float2 g0 = unpack2(ac0[p]); g0.x = siluf(g0.x); g0.y = siluf(g0.y);
            float2 g1 = unpack2(ac1[p]); g1.x = siluf(g1.x); g1.y = siluf(g1.y);
            float2 g2 = unpack2(ac2[p]); g2.x = siluf(g2.x); g2.y = siluf(g2.y);
            float2 g3 = unpack2(ac3[p]); g3.x = siluf(g3.x); g3.y = siluf(g3.y);
            int j0 = 2 * p, j1 = 2 * p + 1;
            if (validW[j0]) {
                float* zb = &g_z[(size_t)eRowW[j0] * 128];
                reds(zb + L, g0.x);
                reds(zb + L + 32, g1.x);
                reds(zb + L + 64, g2.x);
                reds(zb + L + 96, g3.x);
            }
            if (validW[j1]) {
                float* zb = &g_z[(size_t)eRowW[j1] * 128];
                reds(zb + L, g0.y);
                reds(zb + L + 32, g1.y);
                reds(zb + L + 64, g2.y);
                reds(zb + L + 96, g3.y);
            }
            pco[j0] = g0.x * q0v + g1.x * q1v + g2.x * q2v + g3.x * q3v;
            pco[j1] = g0.y * q0v + g1.y * q1v + g2.y * q2v + g3.y * q3v;
        }
#pragma unroll
        for (int j = 0; j < EPW; j++) {
#pragma unroll
            for (int off = 16; off > 0; off >>= 1)
                pco[j] += __shfl_xor_sync(0xffffffffu, pco[j], off);
        }
#pragma unroll
        for (int j = 0; j < EPW; j++) {
            if (lane == j && validW[j]) {
                float cf = qb + pco[j];
                int dst = eRowW[j];
                reds(&g_vagg[dst * 3 + 0], sm.evu_s[w][j][0] * cf);
                reds(&g_vagg[dst * 3 + 1], sm.evu_s[w][j][1] * cf);
                reds(&g_vagg[dst * 3 + 2], sm.evu_s[w][j][2] * cf);
                reds(&g_deg[dst], 1.0f);
            }
        }
        __syncwarp();  // XP reads done before next tile's staging
    }
}

// ---------------------------------------------------------------- node finalize
__global__ __launch_bounds__(256) void post_kernel(
    const float* __restrict__ s, const float* __restrict__ v,
    const float* __restrict__ mgw2, const float* __restrict__ mgb2,
    const float* __restrict__ upw, const float* __restrict__ upb,
    const float* __restrict__ lng, const float* __restrict__ lnb,
    float* __restrict__ outs, float* __restrict__ outv, int N) {
    __shared__ float mw2t[64][132];
    __shared__ float upwt[64][68];
    __shared__ float zs[4][132];
    __shared__ float xs[4][68];
    __shared__ float sn[4][68];
    const int tid = threadIdx.x;
    for (int idx = tid; idx < 128 * 64; idx += 256) {
        int k = idx >> 6, f = idx & 63;
        mw2t[f][k] = mgw2[idx];
    }
    for (int idx = tid; idx < 64 * 64; idx += 256) {
        int k = idx >> 6, f = idx & 63;
        upwt[f][k] = upw[idx];
    }
    __syncthreads();
    const int slot = tid >> 6, f = tid & 63;
    for (int n0 = blockIdx.x * 4; n0 < N; n0 += gridDim.x * 4) {
        int n = n0 + slot;
        bool ok = (n < N);
        zs[slot][f]      = ok ? g_z[n * 128 + f] : 0.0f;
        zs[slot][64 + f] = ok ? g_z[n * 128 + 64 + f] : 0.0f;
        __syncthreads();
        float degv = ok ? g_deg[n] : 0.0f;
        float acc = degv * mgb2[f];
#pragma unroll 4
        for (int k = 0; k < 128; k += 4) {
            float4 w = *(const float4*)&mw2t[f][k];
            float4 x = *(const float4*)&zs[slot][k];
            acc += w.x * x.x + w.y * x.y + w.z * x.z + w.w * x.w;
        }
        xs[slot][f] = siluf(acc);
        __syncthreads();
        float acc2 = upb[f];
#pragma unroll 4
        for (int k = 0; k < 64; k += 4) {
            float4 w = *(const float4*)&upwt[f][k];
            float4 x = *(const float4*)&xs[slot][k];
            acc2 += w.x * x.x + w.y * x.y + w.z * x.z + w.w * x.w;
        }
        float snew = ok ? (s[n * 64 + f] + acc2) : 0.0f;
        sn[slot][f] = snew;
        __syncthreads();
        float sum = 0.0f, sq = 0.0f;
#pragma unroll 4
        for (int k = 0; k < 64; k += 4) {
            float4 t = *(const float4*)&sn[slot][k];
            sum += t.x + t.y + t.z + t.w;
            sq += t.x * t.x + t.y * t.y + t.z * t.z + t.w * t.w;
        }
        float mu = sum * (1.0f / 64.0f);
        float var = sq * (1.0f / 64.0f) - mu * mu;
        if (ok) {
            outs[n * 64 + f] = (snew - mu) * rsqrtf(var + 1e-5f) * lng[f] + lnb[f];
            if (f < 3) {
                float v0 = v[n * 3 + 0] + g_vagg[n * 3 + 0];
                float v1 = v[n * 3 + 1] + g_vagg[n * 3 + 1];
                float v2 = v[n * 3 + 2] + g_vagg[n * 3 + 2];
                float nrm = sqrtf(v0 * v0 + v1 * v1 + v2 * v2);
                float inv = 1.0f / fmaxf(nrm, 1e-6f);
                float val = (f == 0) ? v0 : (f == 1) ? v1 : v2;
                outv[n * 3 + f] = val * inv;
            }
        }
        __syncthreads();
    }
}

// ---------------------------------------------------------------- launch
extern "C" void kernel_launch(void* const* d_in, const int* in_sizes, int n_in,
                              void* d_out, int out_size) {
    const float* s    = (const float*)d_in[0];
    const float* v    = (const float*)d_in[1];
    const int*   ei   = (const int*)d_in[2];
    const float* ea   = (const float*)d_in[3];
    const float* evu  = (const float*)d_in[4];
    const float* ngw1 = (const float*)d_in[5];
    const float* ngb1 = (const float*)d_in[6];
    const float* ngw2 = (const float*)d_in[7];
    const float* ngb2 = (const float*)d_in[8];
    const float* egw1 = (const float*)d_in[9];
    const float* egb1 = (const float*)d_in[10];
    const float* egw2 = (const float*)d_in[11];
    const float* egb2 = (const float*)d_in[12];
    const float* mgw1 = (const float*)d_in[13];
    const float* mgb1 = (const float*)d_in[14];
    const float* mgw2 = (const float*)d_in[15];
    const float* mgb2 = (const float*)d_in[16];
    const float* pew  = (const float*)d_in[17];
    const float* peb  = (const float*)d_in[18];
    const float* upw  = (const float*)d_in[19];
    const float* upb  = (const float*)d_in[20];
    const float* lng  = (const float*)d_in[21];
    const float* lnb  = (const float*)d_in[22];

    const int N = in_sizes[0] / 64;
    const int E = in_sizes[2] / 2;

    float* outs = (float*)d_out;
    float* outv = outs + (size_t)N * 64;

    int nsm = 148;
    cudaDeviceGetAttribute(&nsm, cudaDevAttrMultiProcessorCount, 0);

    zero_kernel<<<512, 256>>>(N * 128, N * 3, N);
    pre_kernel<<<1184, 256>>>(s, ngw1, N);
    preW_kernel<<<128, 256>>>(ngw2, ngb2, egw2, egb2, mgw1, mgb1, mgw2, mgb2, pew, peb);

    cudaFuncSetAttribute(edge_kernel, cudaFuncAttributeMaxDynamicSharedMemorySize,
                         (int)sizeof(EdgeSmem));
    edge_kernel<<<nsm, 512, sizeof(EdgeSmem)>>>(
        v, ei, ea, evu, ngw1, ngb1, egw1, egb1, N, E);

    post_kernel<<<1184, 256>>>(s, v, mgw2, mgb2, upw, upb, lng, lnb, outs, outv, N);
}

// round 10
// speedup vs baseline: 1.1004x; 1.0091x over previous
#include <cuda_runtime.h>
#include <cuda_bf16.h>
#include <stdint.h>
#include <math.h>

#define MAXN 50000
#define MAXE 800000

// ---- device scratch (allocation-free rule) ----
__device__ float g_P[MAXN * 64];      // s @ ng_w1[0:64]
__device__ float g_z[MAXN * 128];     // segsum(silu(hm))
__device__ float g_vagg[MAXN * 3];
__device__ float g_deg[MAXN];
__device__ float g_Wpt[128 * 192];    // fused W' transposed: [o][r]
__device__ float g_b1p[128];          // fused bias into hm
__device__ float g_q[128];            // mg_w2 @ pe_w
__device__ float g_qb[1];             // b_mg2 @ pe_w + pe_b

__device__ __forceinline__ float siluf(float x) { return x / (1.0f + __expf(-x)); }

__device__ __forceinline__ void reds(float* p, float v) {
    asm volatile("red.global.add.f32 [%0], %1;" :: "l"(p), "f"(v) : "memory");
}
__device__ __forceinline__ void redv2(float* p, float a, float b) {
    asm volatile("red.global.add.v2.f32 [%0], {%1,%2};"
                 :: "l"(p), "f"(a), "f"(b) : "memory");
}

// ---- packed f32x2 helpers (Blackwell) ----
typedef unsigned long long u64t;
__device__ __forceinline__ u64t pack2(float x, float y) {
    u64t r; asm("mov.b64 %0, {%1,%2};" : "=l"(r) : "f"(x), "f"(y)); return r;
}
__device__ __forceinline__ float2 unpack2(u64t v) {
    float2 r; asm("mov.b64 {%0,%1}, %2;" : "=f"(r.x), "=f"(r.y) : "l"(v)); return r;
}
__device__ __forceinline__ void ffma2(u64t& d, u64t a, u64t b) {
    asm("fma.rn.f32x2 %0, %1, %2, %0;" : "+l"(d) : "l"(a), "l"(b));
}

// ---- warp MMA helpers (sm_80+ vocabulary, safe on compute_103) ----
__device__ __forceinline__ uint32_t smem_u32(const void* p) {
    uint32_t a;
    asm("{ .reg .u64 t; cvta.to.shared.u64 t, %1; cvt.u32.u64 %0, t; }" : "=r"(a) : "l"(p));
    return a;
}
__device__ __forceinline__ void mma_bf16(float* d, const uint32_t* a, const uint32_t* b) {
    asm volatile(
        "mma.sync.aligned.m16n8k16.row.col.f32.bf16.bf16.f32 "
        "{%0,%1,%2,%3}, {%4,%5,%6,%7}, {%8,%9}, {%0,%1,%2,%3};"
        : "+f"(d[0]), "+f"(d[1]), "+f"(d[2]), "+f"(d[3])
        : "r"(a[0]), "r"(a[1]), "r"(a[2]), "r"(a[3]), "r"(b[0]), "r"(b[1]));
}
__device__ __forceinline__ void ldsm4(uint32_t* r, uint32_t addr) {
    asm volatile("ldmatrix.sync.aligned.m8n8.x4.shared.b16 {%0,%1,%2,%3}, [%4];"
                 : "=r"(r[0]), "=r"(r[1]), "=r"(r[2]), "=r"(r[3]) : "r"(addr));
}
__device__ __forceinline__ void ldsm2(uint32_t* r, uint32_t addr) {
    asm volatile("ldmatrix.sync.aligned.m8n8.x2.shared.b16 {%0,%1}, [%2];"
                 : "=r"(r[0]), "=r"(r[1]) : "r"(addr));
}
__device__ __forceinline__ uint32_t sw(uint32_t b) { return b ^ ((b >> 3) & 0x70u); }

// blocked-atom SW128 byte offset in a [128 rows x 192 cols] bf16 tile
// atom = 8 rows x 64 cols (128B wide); 16 row-atoms, 3 col-atoms
__device__ __forceinline__ uint32_t xoff(int row, int col) {
    uint32_t b = (uint32_t)((row >> 3) + (col >> 6) * 16) * 1024u
               + (uint32_t)(row & 7) * 128u + (uint32_t)(col & 63) * 2u;
    return sw(b);
}
__device__ __forceinline__ void storex(char* ah, char* al, int row, int col, float v) {
    uint32_t o = xoff(row, col);
    __nv_bfloat16 h = __float2bfloat16(v);
    float rem = v - __bfloat162float(h);
    *(__nv_bfloat16*)(ah + o) = h;
    *(__nv_bfloat16*)(al + o) = __float2bfloat16(rem);
}

// ---- smem layout (bytes) ----
#define OFF_AH 0
#define OFF_AL 49152
#define OFF_BH 98304
#define OFF_BL 147456
#define OFF_EGW 196608     // float[64*68] eg_w1 transposed
#define OFF_EAP 214016     // float[16][132] per-warp ea staging
#define OFF_Q 222464       // float[128]
#define OFF_B1P 222976     // float[128]
#define OFF_W65 223488     // float[64]
#define OFF_BNG 223744     // float[64]
#define OFF_BEG 224000     // float[64]
#define OFF_RESI 224256    // float[128]
#define OFF_RESJ 224768    // float[128]
#define OFF_EVU 225280     // float[128][3]
#define OFF_CROSS 226816   // float[128]
#define OFF_EROW 227328    // int[128]
#define OFF_ECOL 227840    // int[128]
#define OFF_VALID 228352   // int[128]
#define OFF_QB 228864
#define EDGE_SMEM_TOTAL 228872

// ---------------------------------------------------------------- zero scratch
__global__ void zero_kernel(int n128, int n3, int n1) {
    int i = blockIdx.x * blockDim.x + threadIdx.x;
    int stride = gridDim.x * blockDim.x;
    for (int k = i; k < n128; k += stride) g_z[k] = 0.0f;
    for (int k = i; k < n3; k += stride) g_vagg[k] = 0.0f;
    for (int k = i; k < n1; k += stride) g_deg[k] = 0.0f;
}

// ---------------------------------------------------------------- P = s @ ng_w1[0:64,:]
__global__ __launch_bounds__(256) void pre_kernel(const float* __restrict__ s,
                                                  const float* __restrict__ ngw1, int N) {
    __shared__ float wt[64][68];
    __shared__ float xs[4][68];
    const int tid = threadIdx.x;
    for (int idx = tid; idx < 64 * 64; idx += 256) {
        int k = idx >> 6, f = idx & 63;
        wt[f][k] = ngw1[idx];
    }
    __syncthreads();
    const int slot = tid >> 6, f = tid & 63;
    for (int n0 = blockIdx.x * 4; n0 < N; n0 += gridDim.x * 4) {
        int n = n0 + slot;
        xs[slot][f] = (n < N) ? s[n * 64 + f] : 0.0f;
        __syncthreads();
        float acc = 0.0f;
#pragma unroll 4
        for (int k = 0; k < 64; k += 4) {
            float4 w = *(const float4*)&wt[f][k];
            float4 x = *(const float4*)&xs[slot][k];
            acc += w.x * x.x + w.y * x.y + w.z * x.z + w.w * x.w;
        }
        if (n < N) g_P[n * 64 + f] = acc;
        __syncthreads();
    }
}

// ---------------------------------------------------------------- fold weights
__global__ void preW_kernel(const float* __restrict__ ngw2, const float* __restrict__ ngb2,
                            const float* __restrict__ egw2, const float* __restrict__ egb2,
                            const float* __restrict__ mgw1, const float* __restrict__ mgb1,
                            const float* __restrict__ mgw2, const float* __restrict__ mgb2,
                            const float* __restrict__ pew, const float* __restrict__ peb) {
    int idx = blockIdx.x * blockDim.x + threadIdx.x;
    int stride = gridDim.x * blockDim.x;
    for (int t = idx; t < 128 * 192 + 128 + 128 + 1; t += stride) {
        if (t < 128 * 192) {
            int o = t / 192, r = t % 192;
            int seg = r >> 6, rr = r & 63, koff = seg * 64;
            const float* src = (seg < 2) ? ngw2 : egw2;
            float val = 0.0f;
            for (int k = 0; k < 64; k++)
                val += src[rr * 64 + k] * mgw1[(koff + k) * 128 + o];
            g_Wpt[o * 192 + r] = val;
        } else if (t < 128 * 192 + 128) {
            int o = t - 128 * 192;
            float val = mgb1[o];
            for (int k = 0; k < 64; k++) {
                val += ngb2[k] * (mgw1[k * 128 + o] + mgw1[(64 + k) * 128 + o]);
                val += egb2[k] * mgw1[(128 + k) * 128 + o];
            }
            g_b1p[o] = val;
        } else if (t < 128 * 192 + 256) {
            int o = t - 128 * 192 - 128;
            float val = 0.0f;
            for (int j = 0; j < 64; j++) val += mgw2[o * 64 + j] * pew[j];
            g_q[o] = val;
        } else {
            float val = peb[0];
            for (int j = 0; j < 64; j++) val += mgb2[j] * pew[j];
            g_qb[0] = val;
        }
    }
}

// ---------------------------------------------------------------- fused edge kernel
// Persistent CTA, 512 threads, tile = 128 edges.
// Phase 0: warps 8-11 compute per-edge metadata.
// Phase A: 16 warps build X = [h_i|h_j|h_e] (f32x2 scalar) -> bf16-split tiles AH/AL.
// Phase B/C (fused, warp-local): warp (m,n)-tile of the 128x128 GEMM via
//   mma.sync m16n8k16 bf16 (XhWh + XhWl + XlWh), then fragment-native epilogue:
//   +b1p, silu, red.v2 -> g_z, lane coeff partial -> red v_agg/deg.
__global__ __launch_bounds__(512, 1) void edge_kernel(
    const float* __restrict__ v, const int* __restrict__ ei,
    const float* __restrict__ ea, const float* __restrict__ evu,
    const float* __restrict__ ngw1, const float* __restrict__ ngb1,
    const float* __restrict__ egw1, const float* __restrict__ egb1,
    int N, int E) {
    extern __shared__ char smem[];
    char* AH = smem + OFF_AH;
    char* AL = smem + OFF_AL;
    char* BH = smem + OFF_BH;
    char* BL = smem + OFF_BL;
    float* egw1t = (float*)(smem + OFF_EGW);
    float* eap = (float*)(smem + OFF_EAP);
    float* qs = (float*)(smem + OFF_Q);
    float* b1ps = (float*)(smem + OFF_B1P);
    float* w65s = (float*)(smem + OFF_W65);
    float* bng = (float*)(smem + OFF_BNG);
    float* beg = (float*)(smem + OFF_BEG);
    float* resI = (float*)(smem + OFF_RESI);
    float* resJ = (float*)(smem + OFF_RESJ);
    float* evus = (float*)(smem + OFF_EVU);
    float* crossm = (float*)(smem + OFF_CROSS);
    int* eRow = (int*)(smem + OFF_EROW);
    int* eCol = (int*)(smem + OFF_ECOL);
    int* valid = (int*)(smem + OFF_VALID);
    float* qbp = (float*)(smem + OFF_QB);

    const int tid = threadIdx.x;
    const int lane = tid & 31;
    const int w = tid >> 5;
    const int L = lane;
    const uint32_t sbase = smem_u32(smem);

    // ---- one-time staging ----
    for (int idx = tid; idx < 65 * 64; idx += 512) {
        int k = idx >> 6, f = idx & 63;
        egw1t[f * 68 + k] = egw1[idx];
    }
    for (int idx = tid; idx < 128 * 192; idx += 512) {
        int o = idx / 192, r = idx % 192;
        float val = g_Wpt[idx];
        uint32_t off = xoff(o, r);
        __nv_bfloat16 h = __float2bfloat16(val);
        *(__nv_bfloat16*)(BH + off) = h;
        *(__nv_bfloat16*)(BL + off) = __float2bfloat16(val - __bfloat162float(h));
    }
    if (tid < 64) {
        w65s[tid] = ngw1[64 * 64 + tid];
        bng[tid] = ngb1[tid];
        beg[tid] = egb1[tid];
    } else if (tid < 192) {
        b1ps[tid - 64] = g_b1p[tid - 64];
    } else if (tid < 320) {
        qs[tid - 192] = g_q[tid - 192];
    } else if (tid == 320) {
        qbp[0] = g_qb[0];
    }
    __syncthreads();

    // hoisted per-lane constants (phase A)
    const float be0 = beg[L], be1 = beg[L + 32];
    const float* eg0 = egw1t + L * 68;
    const float* eg1 = egw1t + (L + 32) * 68;
    const float eg0c = eg0[64], eg1c = eg1[64];
    const float w650 = w65s[L], w651 = w65s[L + 32];
    const float bn0 = bng[L], bn1 = bng[L + 32];
    float* eapw = eap + w * 132;

    // MMA warp-tile constants: 4 M-groups (32 edges) x 4 N-groups (32 cols)
    const int mbase = (w & 3) * 32;
    const int ncol = w >> 2;
    const int gID = lane >> 2, tig = lane & 3;
    uint32_t arow[2];
#pragma unroll
    for (int mb = 0; mb < 2; mb++) {
        int row = mbase + mb * 16 + (lane & 15);
        arow[mb] = (uint32_t)((row >> 3) * 1024 + (row & 7) * 128);
    }
    const uint32_t acoll = (uint32_t)((lane >> 4) * 8);
    uint32_t brow[4];
#pragma unroll
    for (int nf = 0; nf < 4; nf++)
        brow[nf] = (uint32_t)((ncol * 4 + nf) * 1024 + (lane & 7) * 128);
    const uint32_t bcoll = (uint32_t)(((lane >> 3) & 1) * 8);
    const float qb4 = 0.25f * qbp[0];

    for (int base = blockIdx.x * 128; base < E; base += gridDim.x * 128) {
        // ---- phase 0: metadata (warps 8-11) ----
        if (w >= 8 && w < 12) {
            int local = tid - 256;
            int e = base + local;
            int ok = (e < E);
            int r = 0, c = 0;
            float rI = 0.f, rJ = 0.f, cm = 0.f, u0 = 0.f, u1 = 0.f, u2 = 0.f;
            if (ok) {
                r = ei[e]; c = ei[E + e];
                float vx = v[r * 3 + 0], vy = v[r * 3 + 1], vz = v[r * 3 + 2];
                float wx = v[c * 3 + 0], wy = v[c * 3 + 1], wz = v[c * 3 + 2];
                u0 = evu[e * 3 + 0]; u1 = evu[e * 3 + 1]; u2 = evu[e * 3 + 2];
                rI = 1.0f - (vx * u0 + vy * u1 + vz * u2);
                rJ = 1.0f + (wx * u0 + wy * u1 + wz * u2);
                float cx = vy * wz - vz * wy;
                float cy = vz * wx - vx * wz;
                float cz = vx * wy - vy * wx;
                cm = sqrtf(cx * cx + cy * cy + cz * cz);
            }
            valid[local] = ok;
            eRow[local] = r;
            eCol[local] = c;
            resI[local] = rI; resJ[local] = rJ; crossm[local] = cm;
            evus[local * 3 + 0] = u0;
            evus[local * 3 + 1] = u1;
            evus[local * 3 + 2] = u2;
        }
        __syncthreads();

        // ---- phase A: 4 warp-local passes, 2 edges (1 pair) per warp per pass ----
#pragma unroll
        for (int pass = 0; pass < 4; pass++) {
            const int j0 = pass * 32 + 2 * w, j1 = j0 + 1;
            const int e0 = base + j0, e1 = e0 + 1;
            {
                float2 a0 = make_float2(0.f, 0.f), a1 = a0;
                if (e0 < E) a0 = *(const float2*)&ea[(size_t)e0 * 64 + 2 * L];
                if (e1 < E) a1 = *(const float2*)&ea[(size_t)e1 * 64 + 2 * L];
                *(float4*)&eapw[4 * L] = make_float4(a0.x, a1.x, a0.y, a1.y);
                if (L < 2) eapw[128 + L] = crossm[j0 + L];
            }
            __syncwarp();
            // h_e GEMM (packed over the pair)
            u64t h0 = pack2(be0, be0), h1 = pack2(be1, be1);
#pragma unroll 8
            for (int k = 0; k < 64; k += 2) {
                float2 wA = *(const float2*)&eg0[k];
                float2 wB = *(const float2*)&eg1[k];
                ulonglong2 xq = *(const ulonglong2*)&eapw[2 * k];
                ffma2(h0, xq.x, pack2(wA.x, wA.x));
                ffma2(h1, xq.x, pack2(wB.x, wB.x));
                ffma2(h0, xq.y, pack2(wA.y, wA.y));
                ffma2(h1, xq.y, pack2(wB.y, wB.y));
            }
            {
                u64t cr = *(const u64t*)&eapw[128];
                ffma2(h0, cr, pack2(eg0c, eg0c));
                ffma2(h1, cr, pack2(eg1c, eg1c));
            }
            float2 t0 = unpack2(h0), t1 = unpack2(h1);
            storex(AH, AL, j0, 128 + L, siluf(t0.x));
            storex(AH, AL, j1, 128 + L, siluf(t0.y));
            storex(AH, AL, j0, 128 + L + 32, siluf(t1.x));
            storex(AH, AL, j1, 128 + L + 32, siluf(t1.y));
            // h_i / h_j
            {
                int ok0 = valid[j0], ok1 = valid[j1];
                float a0 = 0.f, b0 = 0.f, c0 = 0.f, d0 = 0.f;
                float a1 = 0.f, b1 = 0.f, c1 = 0.f, d1 = 0.f;
                if (ok0) {
                    int r = eRow[j0], c = eCol[j0];
                    a0 = g_P[r * 64 + L];  b0 = g_P[r * 64 + L + 32];
                    c0 = g_P[c * 64 + L];  d0 = g_P[c * 64 + L + 32];
                }
                if (ok1) {
                    int r = eRow[j1], c = eCol[j1];
                    a1 = g_P[r * 64 + L];  b1 = g_P[r * 64 + L + 32];
                    c1 = g_P[c * 64 + L];  d1 = g_P[c * 64 + L + 32];
                }
                float rI0 = resI[j0], rI1 = resI[j1];
                float rJ0 = resJ[j0], rJ1 = resJ[j1];
                storex(AH, AL, j0, L, siluf(a0 + rI0 * w650 + bn0));
                storex(AH, AL, j1, L, siluf(a1 + rI1 * w650 + bn0));
                storex(AH, AL, j0, L + 32, siluf(b0 + rI0 * w651 + bn1));
                storex(AH, AL, j1, L + 32, siluf(b1 + rI1 * w651 + bn1));
                storex(AH, AL, j0, 64 + L, siluf(c0 + rJ0 * w650 + bn0));
                storex(AH, AL, j1, 64 + L, siluf(c1 + rJ1 * w650 + bn0));
                storex(AH, AL, j0, 64 + L + 32, siluf(d0 + rJ0 * w651 + bn1));
                storex(AH, AL, j1, 64 + L + 32, siluf(d1 + rJ1 * w651 + bn1));
            }
            __syncwarp();
        }
        __syncthreads();

        // ---- phase B: warp-tile MMA (32 edges x 32 cols per warp) ----
        float d[2][4][4];
#pragma unroll
        for (int mb = 0; mb < 2; mb++)
#pragma unroll
            for (int nf = 0; nf < 4; nf++)
#pragma unroll
                for (int i = 0; i < 4; i++) d[mb][nf][i] = 0.0f;

        // pass 1: Xh * (Wh + Wl)
#pragma unroll
        for (int kf = 0; kf < 12; kf++) {
            uint32_t acol = (uint32_t)kf * 16 + acoll;
            uint32_t acp = (acol >> 6) * 16384 + (acol & 63) * 2;
            uint32_t a0[4], a1[4];
            ldsm4(a0, sbase + OFF_AH + sw(arow[0] + acp));
            ldsm4(a1, sbase + OFF_AH + sw(arow[1] + acp));
            uint32_t bcol = (uint32_t)kf * 16 + bcoll;
            uint32_t bcp = (bcol >> 6) * 16384 + (bcol & 63) * 2;
#pragma unroll
            for (int nf = 0; nf < 4; nf++) {
                uint32_t bo = sw(brow[nf] + bcp);
                uint32_t bh[2], bl[2];
                ldsm2(bh, sbase + OFF_BH + bo);
                ldsm2(bl, sbase + OFF_BL + bo);
                mma_bf16(d[0][nf], a0, bh);
                mma_bf16(d[1][nf], a1, bh);
                mma_bf16(d[0][nf], a0, bl);
                mma_bf16(d[1][nf], a1, bl);
            }
        }
        // pass 2: Xl * Wh
#pragma unroll
        for (int kf = 0; kf < 12; kf++) {
            uint32_t acol = (uint32_t)kf * 16 + acoll;
            uint32_t acp = (acol >> 6) * 16384 + (acol & 63) * 2;
            uint32_t a0[4], a1[4];
            ldsm4(a0, sbase + OFF_AL + sw(arow[0] + acp));
            ldsm4(a1, sbase + OFF_AL + sw(arow[1] + acp));
            uint32_t bcol = (uint32_t)kf * 16 + bcoll;
            uint32_t bcp = (bcol >> 6) * 16384 + (bcol & 63) * 2;
#pragma unroll
            for (int nf = 0; nf < 4; nf++) {
                uint32_t bo = sw(brow[nf] + bcp);
                uint32_t bh[2];
                ldsm2(bh, sbase + OFF_BH + bo);
                mma_bf16(d[0][nf], a0, bh);
                mma_bf16(d[1][nf], a1, bh);
            }
        }

        // ---- phase C: fragment-native epilogue ----
#pragma unroll
        for (int mb = 0; mb < 2; mb++) {
#pragma unroll
            for (int half = 0; half < 2; half++) {
                int erow = mbase + mb * 16 + gID + half * 8;
                int ok = valid[erow];
                int dst = eRow[erow];
                float part = 0.0f;
#pragma unroll
                for (int nf = 0; nf < 4; nf++) {
                    int col = ncol * 32 + nf * 8 + 2 * tig;
                    float g0 = siluf(d[mb][nf][half * 2 + 0] + b1ps[col]);
                    float g1 = siluf(d[mb][nf][half * 2 + 1] + b1ps[col + 1]);
                    part += g0 * qs[col] + g1 * qs[col + 1];
                    if (ok) redv2(&g_z[(size_t)dst * 128 + col], g0, g1);
                }
                part += __shfl_xor_sync(0xffffffffu, part, 1);
                part += __shfl_xor_sync(0xffffffffu, part, 2);
                if (ok && tig == 0) {
                    float cf = qb4 + part;
                    reds(&g_vagg[dst * 3 + 0], evus[erow * 3 + 0] * cf);
                    reds(&g_vagg[dst * 3 + 1], evus[erow * 3 + 1] * cf);
                    reds(&g_vagg[dst * 3 + 2], evus[erow * 3 + 2] * cf);
                    if (ncol == 0) reds(&g_deg[dst], 1.0f);
                }
            }
        }
        __syncthreads();  // protect AH/AL + metadata before next tile
    }
}

// ---------------------------------------------------------------- node finalize
__global__ __launch_bounds__(256) void post_kernel(
    const float* __restrict__ s, const float* __restrict__ v,
    const float* __restrict__ mgw2, const float* __restrict__ mgb2,
    const float* __restrict__ upw, const float* __restrict__ upb,
    const float* __restrict__ lng, const float* __restrict__ lnb,
    float* __restrict__ outs, float* __restrict__ outv, int N) {
    __shared__ float mw2t[64][132];
    __shared__ float upwt[64][68];
    __shared__ float zs[4][132];
    __shared__ float xs[4][68];
    __shared__ float sn[4][68];
    const int tid = threadIdx.x;
    for (int idx = tid; idx < 128 * 64; idx += 256) {
        int k = idx >> 6, f = idx & 63;
        mw2t[f][k] = mgw2[idx];
    }
    for (int idx = tid; idx < 64 * 64; idx += 256) {
        int k = idx >> 6, f = idx & 63;
        upwt[f][k] = upw[idx];
    }
    __syncthreads();
    const int slot = tid >> 6, f = tid & 63;
    for (int n0 = blockIdx.x * 4; n0 < N; n0 += gridDim.x * 4) {
        int n = n0 + slot;
        bool ok = (n < N);
        zs[slot][f]      = ok ? g_z[n * 128 + f] : 0.0f;
        zs[slot][64 + f] = ok ? g_z[n * 128 + 64 + f] : 0.0f;
        __syncthreads();
        float degv = ok ? g_deg[n] : 0.0f;
        float acc = degv * mgb2[f];
#pragma unroll 4
        for (int k = 0; k < 128; k += 4) {
            float4 w = *(const float4*)&mw2t[f][k];
            float4 x = *(const float4*)&zs[slot][k];
            acc += w.x * x.x + w.y * x.y + w.z * x.z + w.w * x.w;
        }
        xs[slot][f] = siluf(acc);
        __syncthreads();
        float acc2 = upb[f];
#pragma unroll 4
        for (int k = 0; k < 64; k += 4) {
            float4 w = *(const float4*)&upwt[f][k];
            float4 x = *(const float4*)&xs[slot][k];
            acc2 += w.x * x.x + w.y * x.y + w.z * x.z + w.w * x.w;
        }
        float snew = ok ? (s[n * 64 + f] + acc2) : 0.0f;
        sn[slot][f] = snew;
        __syncthreads();
        float sum = 0.0f, sq = 0.0f;
#pragma unroll 4
        for (int k = 0; k < 64; k += 4) {
            float4 t = *(const float4*)&sn[slot][k];
            sum += t.x + t.y + t.z + t.w;
            sq += t.x * t.x + t.y * t.y + t.z * t.z + t.w * t.w;
        }
        float mu = sum * (1.0f / 64.0f);
        float var = sq * (1.0f / 64.0f) - mu * mu;
        if (ok) {
            outs[n * 64 + f] = (snew - mu) * rsqrtf(var + 1e-5f) * lng[f] + lnb[f];
            if (f < 3) {
                float v0 = v[n * 3 + 0] + g_vagg[n * 3 + 0];
                float v1 = v[n * 3 + 1] + g_vagg[n * 3 + 1];
                float v2 = v[n * 3 + 2] + g_vagg[n * 3 + 2];
                float nrm = sqrtf(v0 * v0 + v1 * v1 + v2 * v2);
                float inv = 1.0f / fmaxf(nrm, 1e-6f);
                float val = (f == 0) ? v0 : (f == 1) ? v1 : v2;
                outv[n * 3 + f] = val * inv;
            }
        }
        __syncthreads();
    }
}

// ---------------------------------------------------------------- launch
extern "C" void kernel_launch(void* const* d_in, const int* in_sizes, int n_in,
                              void* d_out, int out_size) {
    const float* s    = (const float*)d_in[0];
    const float* v    = (const float*)d_in[1];
    const int*   ei   = (const int*)d_in[2];
    const float* ea   = (const float*)d_in[3];
    const float* evu  = (const float*)d_in[4];
    const float* ngw1 = (const float*)d_in[5];
    const float* ngb1 = (const float*)d_in[6];
    const float* ngw2 = (const float*)d_in[7];
    const float* ngb2 = (const float*)d_in[8];
    const float* egw1 = (const float*)d_in[9];
    const float* egb1 = (const float*)d_in[10];
    const float* egw2 = (const float*)d_in[11];
    const float* egb2 = (const float*)d_in[12];
    const float* mgw1 = (const float*)d_in[13];
    const float* mgb1 = (const float*)d_in[14];
    const float* mgw2 = (const float*)d_in[15];
    const float* mgb2 = (const float*)d_in[16];
    const float* pew  = (const float*)d_in[17];
    const float* peb  = (const float*)d_in[18];
    const float* upw  = (const float*)d_in[19];
    const float* upb  = (const float*)d_in[20];
    const float* lng  = (const float*)d_in[21];
    const float* lnb  = (const float*)d_in[22];

    const int N = in_sizes[0] / 64;
    const int E = in_sizes[2] / 2;

    float* outs = (float*)d_out;
    float* outv = outs + (size_t)N * 64;

    int nsm = 148;
    cudaDeviceGetAttribute(&nsm, cudaDevAttrMultiProcessorCount, 0);

    zero_kernel<<<512, 256>>>(N * 128, N * 3, N);
    pre_kernel<<<1184, 256>>>(s, ngw1, N);
    preW_kernel<<<128, 256>>>(ngw2, ngb2, egw2, egb2, mgw1, mgb1, mgw2, mgb2, pew, peb);

    cudaFuncSetAttribute(edge_kernel, cudaFuncAttributeMaxDynamicSharedMemorySize,
                         EDGE_SMEM_TOTAL);
    edge_kernel<<<nsm, 512, EDGE_SMEM_TOTAL>>>(
        v, ei, ea, evu, ngw1, ngb1, egw1, egb1, N, E);

    post_kernel<<<1184, 256>>>(s, v, mgw2, mgb2, upw, upb, lng, lnb, outs, outv, N);
}

// round 11
// speedup vs baseline: 1.3264x; 1.2054x over previous
#include <cuda_runtime.h>
#include <cuda_bf16.h>
#include <stdint.h>
#include <math.h>

#define MAXN 50000
#define MAXE 800000

// ---- device scratch (allocation-free rule) ----
__device__ float g_P[MAXN * 64];      // s @ ng_w1[0:64]
__device__ float g_z[MAXN * 128];     // segsum(silu(hm))
__device__ float g_vagg[MAXN * 3];
__device__ float g_deg[MAXN];
__device__ float g_Wpt[128 * 192];    // fused W' transposed: [o][r]
__device__ float g_b1p[128];          // fused bias into hm
__device__ float g_q[128];            // mg_w2 @ pe_w
__device__ float g_qb[1];             // b_mg2 @ pe_w + pe_b

__device__ __forceinline__ float siluf(float x) { return x / (1.0f + __expf(-x)); }

__device__ __forceinline__ void reds(float* p, float v) {
    asm volatile("red.global.add.f32 [%0], %1;" :: "l"(p), "f"(v) : "memory");
}
__device__ __forceinline__ void redv2(float* p, float a, float b) {
    asm volatile("red.global.add.v2.f32 [%0], {%1,%2};"
                 :: "l"(p), "f"(a), "f"(b) : "memory");
}

// ---- warp MMA helpers (sm_80+ vocabulary, safe on compute_103) ----
__device__ __forceinline__ uint32_t smem_u32(const void* p) {
    uint32_t a;
    asm("{ .reg .u64 t; cvta.to.shared.u64 t, %1; cvt.u32.u64 %0, t; }" : "=r"(a) : "l"(p));
    return a;
}
__device__ __forceinline__ void mma_bf16(float* d, const uint32_t* a, const uint32_t* b) {
    asm volatile(
        "mma.sync.aligned.m16n8k16.row.col.f32.bf16.bf16.f32 "
        "{%0,%1,%2,%3}, {%4,%5,%6,%7}, {%8,%9}, {%0,%1,%2,%3};"
        : "+f"(d[0]), "+f"(d[1]), "+f"(d[2]), "+f"(d[3])
        : "r"(a[0]), "r"(a[1]), "r"(a[2]), "r"(a[3]), "r"(b[0]), "r"(b[1]));
}
__device__ __forceinline__ void ldsm4(uint32_t* r, uint32_t addr) {
    asm volatile("ldmatrix.sync.aligned.m8n8.x4.shared.b16 {%0,%1,%2,%3}, [%4];"
                 : "=r"(r[0]), "=r"(r[1]), "=r"(r[2]), "=r"(r[3]) : "r"(addr));
}
__device__ __forceinline__ void ldsm2(uint32_t* r, uint32_t addr) {
    asm volatile("ldmatrix.sync.aligned.m8n8.x2.shared.b16 {%0,%1}, [%2];"
                 : "=r"(r[0]), "=r"(r[1]) : "r"(addr));
}
__device__ __forceinline__ uint32_t sw(uint32_t b) { return b ^ ((b >> 3) & 0x70u); }

// blocked-atom SW128 byte offset in a [rows x cols] bf16 tile with 64-col atoms,
// 16 row-atoms per col-atom (A tiles). atom = 8 rows x 64 cols (128B wide).
__device__ __forceinline__ uint32_t xoff(int row, int col) {
    uint32_t b = (uint32_t)((row >> 3) + (col >> 6) * 16) * 1024u
               + (uint32_t)(row & 7) * 128u + (uint32_t)(col & 63) * 2u;
    return sw(b);
}
// split-store one float into hi/lo bf16 tiles at a precomputed (unswizzled-free) offset
__device__ __forceinline__ void storex(char* ah, char* al, int row, int col, float v) {
    uint32_t o = xoff(row, col);
    __nv_bfloat16 h = __float2bfloat16(v);
    float rem = v - __bfloat162float(h);
    *(__nv_bfloat16*)(ah + o) = h;
    *(__nv_bfloat16*)(al + o) = __float2bfloat16(rem);
}
// split-store an adjacent col pair (packed bf16x2, single STS.32 per tile)
__device__ __forceinline__ void store_pair(char* ah, char* al, uint32_t o, float x, float y) {
    __nv_bfloat162 h = __floats2bfloat162_rn(x, y);
    __nv_bfloat162 l = __floats2bfloat162_rn(x - __bfloat162float(h.x),
                                             y - __bfloat162float(h.y));
    *(__nv_bfloat162*)(ah + o) = h;
    *(__nv_bfloat162*)(al + o) = l;
}

// ---- smem layout (bytes) ----
#define OFF_AH 0           // X tile hi: 128 rows x 192 cols bf16 (3 col-atoms)
#define OFF_AL 49152
#define OFF_BH 98304       // W' tile hi: 128 out x 192 k bf16
#define OFF_BL 147456
#define OFF_EGBH 196608    // eg_w1 B-tile hi: 64 out x 64 k bf16 (8KB)
#define OFF_EGBL 204800
#define OFF_Q 212992       // float[128]
#define OFF_B1P 213504     // float[128]
#define OFF_W64S 214016    // float[64]  eg_w1 row 64 (cross coeff)
#define OFF_BEGS 214272    // float[64]  eg bias
#define OFF_W65 214528     // float[64]  ng_w1 row 64
#define OFF_BNG 214784     // float[64]  ng bias
#define OFF_RESI 215040    // float[128]
#define OFF_RESJ 215552    // float[128]
#define OFF_EVU 216064     // float[128][3]
#define OFF_CROSS 217600   // float[128]
#define OFF_EROW 218112    // int[128]
#define OFF_ECOL 218624    // int[128]
#define OFF_VALID 219136   // int[128]
#define OFF_QB 219648
#define EDGE_SMEM_TOTAL 219656

// ---------------------------------------------------------------- zero scratch
__global__ void zero_kernel(int n128, int n3, int n1) {
    int i = blockIdx.x * blockDim.x + threadIdx.x;
    int stride = gridDim.x * blockDim.x;
    for (int k = i; k < n128; k += stride) g_z[k] = 0.0f;
    for (int k = i; k < n3; k += stride) g_vagg[k] = 0.0f;
    for (int k = i; k < n1; k += stride) g_deg[k] = 0.0f;
}

// ---------------------------------------------------------------- P = s @ ng_w1[0:64,:]
__global__ __launch_bounds__(256) void pre_kernel(const float* __restrict__ s,
                                                  const float* __restrict__ ngw1, int N) {
    __shared__ float wt[64][68];
    __shared__ float xs[4][68];
    const int tid = threadIdx.x;
    for (int idx = tid; idx < 64 * 64; idx += 256) {
        int k = idx >> 6, f = idx & 63;
        wt[f][k] = ngw1[idx];
    }
    __syncthreads();
    const int slot = tid >> 6, f = tid & 63;
    for (int n0 = blockIdx.x * 4; n0 < N; n0 += gridDim.x * 4) {
        int n = n0 + slot;
        xs[slot][f] = (n < N) ? s[n * 64 + f] : 0.0f;
        __syncthreads();
        float acc = 0.0f;
#pragma unroll 4
        for (int k = 0; k < 64; k += 4) {
            float4 w = *(const float4*)&wt[f][k];
            float4 x = *(const float4*)&xs[slot][k];
            acc += w.x * x.x + w.y * x.y + w.z * x.z + w.w * x.w;
        }
        if (n < N) g_P[n * 64 + f] = acc;
        __syncthreads();
    }
}

// ---------------------------------------------------------------- fold weights
__global__ void preW_kernel(const float* __restrict__ ngw2, const float* __restrict__ ngb2,
                            const float* __restrict__ egw2, const float* __restrict__ egb2,
                            const float* __restrict__ mgw1, const float* __restrict__ mgb1,
                            const float* __restrict__ mgw2, const float* __restrict__ mgb2,
                            const float* __restrict__ pew, const float* __restrict__ peb) {
    int idx = blockIdx.x * blockDim.x + threadIdx.x;
    int stride = gridDim.x * blockDim.x;
    for (int t = idx; t < 128 * 192 + 128 + 128 + 1; t += stride) {
        if (t < 128 * 192) {
            int o = t / 192, r = t % 192;
            int seg = r >> 6, rr = r & 63, koff = seg * 64;
            const float* src = (seg < 2) ? ngw2 : egw2;
            float val = 0.0f;
            for (int k = 0; k < 64; k++)
                val += src[rr * 64 + k] * mgw1[(koff + k) * 128 + o];
            g_Wpt[o * 192 + r] = val;
        } else if (t < 128 * 192 + 128) {
            int o = t - 128 * 192;
            float val = mgb1[o];
            for (int k = 0; k < 64; k++) {
                val += ngb2[k] * (mgw1[k * 128 + o] + mgw1[(64 + k) * 128 + o]);
                val += egb2[k] * mgw1[(128 + k) * 128 + o];
            }
            g_b1p[o] = val;
        } else if (t < 128 * 192 + 256) {
            int o = t - 128 * 192 - 128;
            float val = 0.0f;
            for (int j = 0; j < 64; j++) val += mgw2[o * 64 + j] * pew[j];
            g_q[o] = val;
        } else {
            float val = peb[0];
            for (int j = 0; j < 64; j++) val += mgb2[j] * pew[j];
            g_qb[0] = val;
        }
    }
}

// ---------------------------------------------------------------- fused edge kernel
// Persistent CTA, 512 threads, tile = 128 edges. All GEMMs on mma.sync bf16-split.
// P0: metadata. A1: stage ea (into X atom2) + h_i/h_j (atoms 0/1), packed bf16x2.
// B1: h_e MMA [128x64]@eg_w1[64x64] (3 terms). E1: +cross*w64+bias, silu -> atom2.
// B2: [128x192]@W'[192x128] (3 terms). C: fragment epilogue -> RED scatter.
__global__ __launch_bounds__(512, 1) void edge_kernel(
    const float* __restrict__ v, const int* __restrict__ ei,
    const float* __restrict__ ea, const float* __restrict__ evu,
    const float* __restrict__ ngw1, const float* __restrict__ ngb1,
    const float* __restrict__ egw1, const float* __restrict__ egb1,
    int N, int E) {
    extern __shared__ char smem[];
    char* AH = smem + OFF_AH;
    char* AL = smem + OFF_AL;
    char* BH = smem + OFF_BH;
    char* BL = smem + OFF_BL;
    char* EGBH = smem + OFF_EGBH;
    char* EGBL = smem + OFF_EGBL;
    float* qs = (float*)(smem + OFF_Q);
    float* b1ps = (float*)(smem + OFF_B1P);
    float* w64s = (float*)(smem + OFF_W64S);
    float* begs = (float*)(smem + OFF_BEGS);
    float* w65s = (float*)(smem + OFF_W65);
    float* bng = (float*)(smem + OFF_BNG);
    float* resI = (float*)(smem + OFF_RESI);
    float* resJ = (float*)(smem + OFF_RESJ);
    float* evus = (float*)(smem + OFF_EVU);
    float* crossm = (float*)(smem + OFF_CROSS);
    int* eRow = (int*)(smem + OFF_EROW);
    int* eCol = (int*)(smem + OFF_ECOL);
    int* valid = (int*)(smem + OFF_VALID);
    float* qbp = (float*)(smem + OFF_QB);

    const int tid = threadIdx.x;
    const int lane = tid & 31;
    const int w = tid >> 5;
    const int L = lane;
    const uint32_t sbase = smem_u32(smem);

    // ---- one-time staging ----
    for (int idx = tid; idx < 128 * 192; idx += 512) {
        int o = idx / 192, r = idx % 192;
        float val = g_Wpt[idx];
        uint32_t off = xoff(o, r);
        __nv_bfloat16 h = __float2bfloat16(val);
        *(__nv_bfloat16*)(BH + off) = h;
        *(__nv_bfloat16*)(BL + off) = __float2bfloat16(val - __bfloat162float(h));
    }
    for (int idx = tid; idx < 64 * 64; idx += 512) {
        int k = idx >> 6, n = idx & 63;
        float val = egw1[k * 64 + n];   // B[n][k] = W1[k][n]
        uint32_t off = sw((uint32_t)((n >> 3) * 1024 + (n & 7) * 128 + k * 2));
        __nv_bfloat16 h = __float2bfloat16(val);
        *(__nv_bfloat16*)(EGBH + off) = h;
        *(__nv_bfloat16*)(EGBL + off) = __float2bfloat16(val - __bfloat162float(h));
    }
    if (tid < 64) {
        w64s[tid] = egw1[64 * 64 + tid];
        begs[tid] = egb1[tid];
        w65s[tid] = ngw1[64 * 64 + tid];
        bng[tid] = ngb1[tid];
    } else if (tid < 192) {
        b1ps[tid - 64] = g_b1p[tid - 64];
    } else if (tid < 320) {
        qs[tid - 192] = g_q[tid - 192];
    } else if (tid == 320) {
        qbp[0] = g_qb[0];
    }
    __syncthreads();

    // hoisted per-lane constants
    const float w65a = w65s[2 * L], w65b = w65s[2 * L + 1];
    const float bna = bng[2 * L], bnb = bng[2 * L + 1];

    // warp-tile constants
    const int mbase = (w & 3) * 32;          // M group (shared by B1 and B2)
    const int ncol = w >> 2;                 // B2: N group of 32
    const int nb1 = (w >> 2) * 16;           // B1: N group of 16
    const int gID = lane >> 2, tig = lane & 3;
    uint32_t arow[2];
#pragma unroll
    for (int mb = 0; mb < 2; mb++) {
        int row = mbase + mb * 16 + (lane & 15);
        arow[mb] = (uint32_t)((row >> 3) * 1024 + (row & 7) * 128);
    }
    const uint32_t acoll = (uint32_t)((lane >> 4) * 8);
    uint32_t brow[4];
#pragma unroll
    for (int nf = 0; nf < 4; nf++)
        brow[nf] = (uint32_t)((ncol * 4 + nf) * 1024 + (lane & 7) * 128);
    uint32_t browE[2];
#pragma unroll
    for (int nf = 0; nf < 2; nf++) {
        int nrow = nb1 + nf * 8 + (lane & 7);
        browE[nf] = (uint32_t)((nrow >> 3) * 1024 + (nrow & 7) * 128);
    }
    const uint32_t bcoll = (uint32_t)(((lane >> 3) & 1) * 8);
    const float qb4 = 0.25f * qbp[0];

    for (int base = blockIdx.x * 128; base < E; base += gridDim.x * 128) {
        // ---- P0: metadata (warps 8-11) ----
        if (w >= 8 && w < 12) {
            int local = tid - 256;
            int e = base + local;
            int ok = (e < E);
            int r = 0, c = 0;
            float rI = 0.f, rJ = 0.f, cm = 0.f, u0 = 0.f, u1 = 0.f, u2 = 0.f;
            if (ok) {
                r = ei[e]; c = ei[E + e];
                float vx = v[r * 3 + 0], vy = v[r * 3 + 1], vz = v[r * 3 + 2];
                float wx = v[c * 3 + 0], wy = v[c * 3 + 1], wz = v[c * 3 + 2];
                u0 = evu[e * 3 + 0]; u1 = evu[e * 3 + 1]; u2 = evu[e * 3 + 2];
                rI = 1.0f - (vx * u0 + vy * u1 + vz * u2);
                rJ = 1.0f + (wx * u0 + wy * u1 + wz * u2);
                float cx = vy * wz - vz * wy;
                float cy = vz * wx - vx * wz;
                float cz = vx * wy - vy * wx;
                cm = sqrtf(cx * cx + cy * cy + cz * cz);
            }
            valid[local] = ok;
            eRow[local] = r;
            eCol[local] = c;
            resI[local] = rI; resJ[local] = rJ; crossm[local] = cm;
            evus[local * 3 + 0] = u0;
            evus[local * 3 + 1] = u1;
            evus[local * 3 + 2] = u2;
        }
        __syncthreads();

        // ---- A1: stage ea into X atom2 + h_i/h_j into atoms 0/1 ----
#pragma unroll
        for (int j = 0; j < 8; j++) {
            int erow = w * 8 + j;
            int e = base + erow;
            float2 a = make_float2(0.f, 0.f);
            if (e < E) a = *(const float2*)&ea[(size_t)e * 64 + 2 * L];
            uint32_t o = sw(32768u + (uint32_t)((erow >> 3) * 1024 + (erow & 7) * 128 + 4 * L));
            store_pair(AH, AL, o, a.x, a.y);
        }
#pragma unroll
        for (int j = 0; j < 8; j++) {
            int erow = w * 8 + j;
            int ok = valid[erow];
            float2 pi = make_float2(0.f, 0.f), pj = pi;
            if (ok) {
                int r = eRow[erow], c = eCol[erow];
                pi = *(const float2*)&g_P[r * 64 + 2 * L];
                pj = *(const float2*)&g_P[c * 64 + 2 * L];
            }
            float rI = resI[erow], rJ = resJ[erow];
            float i0 = siluf(pi.x + rI * w65a + bna);
            float i1 = siluf(pi.y + rI * w65b + bnb);
            float j0v = siluf(pj.x + rJ * w65a + bna);
            float j1v = siluf(pj.y + rJ * w65b + bnb);
            uint32_t ro = (uint32_t)((erow >> 3) * 1024 + (erow & 7) * 128 + 4 * L);
            store_pair(AH, AL, sw(ro), i0, i1);
            store_pair(AH, AL, sw(16384u + ro), j0v, j1v);
        }
        __syncthreads();

        // ---- B1: h_e MMA (warp tile 32 edges x 16 out-cols, K=64, 3 terms) ----
        float dE[2][2][4];
#pragma unroll
        for (int mb = 0; mb < 2; mb++)
#pragma unroll
            for (int nf = 0; nf < 2; nf++)
#pragma unroll
                for (int i = 0; i < 4; i++) dE[mb][nf][i] = 0.0f;
#pragma unroll
        for (int kf = 0; kf < 4; kf++) {
            uint32_t ac = (uint32_t)(kf * 16) * 2 + acoll * 2;
            uint32_t ah0[4], ah1[4], al0[4], al1[4];
            ldsm4(ah0, sbase + OFF_AH + sw(32768u + arow[0] + ac));
            ldsm4(ah1, sbase + OFF_AH + sw(32768u + arow[1] + ac));
            ldsm4(al0, sbase + OFF_AL + sw(32768u + arow[0] + ac));
            ldsm4(al1, sbase + OFF_AL + sw(32768u + arow[1] + ac));
            uint32_t bc = (uint32_t)(kf * 16) * 2 + bcoll * 2;
#pragma unroll
            for (int nf = 0; nf < 2; nf++) {
                uint32_t bo = sw(browE[nf] + bc);
                uint32_t bh[2], bl[2];
                ldsm2(bh, sbase + OFF_EGBH + bo);
                ldsm2(bl, sbase + OFF_EGBL + bo);
                mma_bf16(dE[0][nf], ah0, bh);
                mma_bf16(dE[1][nf], ah1, bh);
                mma_bf16(dE[0][nf], ah0, bl);
                mma_bf16(dE[1][nf], ah1, bl);
                mma_bf16(dE[0][nf], al0, bh);
                mma_bf16(dE[1][nf], al1, bh);
            }
        }
        __syncthreads();   // all reads of atom2 (raw ea) complete

        // ---- E1: h_e epilogue -> silu -> split-store into atom2 ----
#pragma unroll
        for (int mb = 0; mb < 2; mb++)
#pragma unroll
            for (int nf = 0; nf < 2; nf++)
#pragma unroll
                for (int half = 0; half < 2; half++) {
                    int row = mbase + mb * 16 + gID + half * 8;
                    int col = nb1 + nf * 8 + 2 * tig;
                    float cm = crossm[row];
                    float v0 = dE[mb][nf][half * 2 + 0] + cm * w64s[col] + begs[col];
                    float v1 = dE[mb][nf][half * 2 + 1] + cm * w64s[col + 1] + begs[col + 1];
                    uint32_t o = sw(32768u +
                        (uint32_t)((row >> 3) * 1024 + (row & 7) * 128 + col * 2));
                    store_pair(AH, AL, o, siluf(v0), siluf(v1));
                }
        __syncthreads();

        // ---- B2: big GEMM (warp tile 32 edges x 32 cols, K=192, 3 terms) ----
        float d[2][4][4];
#pragma unroll
        for (int mb = 0; mb < 2; mb++)
#pragma unroll
            for (int nf = 0; nf < 4; nf++)
#pragma unroll
                for (int i = 0; i < 4; i++) d[mb][nf][i] = 0.0f;
        // pass 1: Xh * (Wh + Wl)
#pragma unroll
        for (int kf = 0; kf < 12; kf++) {
            uint32_t acol = (uint32_t)kf * 16 + acoll;
            uint32_t acp = (acol >> 6) * 16384 + (acol & 63) * 2;
            uint32_t a0[4], a1[4];
            ldsm4(a0, sbase + OFF_AH + sw(arow[0] + acp));
            ldsm4(a1, sbase + OFF_AH + sw(arow[1] + acp));
            uint32_t bcol = (uint32_t)kf * 16 + bcoll;
            uint32_t bcp = (bcol >> 6) * 16384 + (bcol & 63) * 2;
#pragma unroll
            for (int nf = 0; nf < 4; nf++) {
                uint32_t bo = sw(brow[nf] + bcp);
                uint32_t bh[2], bl[2];
                ldsm2(bh, sbase + OFF_BH + bo);
                ldsm2(bl, sbase + OFF_BL + bo);
                mma_bf16(d[0][nf], a0, bh);
                mma_bf16(d[1][nf], a1, bh);
                mma_bf16(d[0][nf], a0, bl);
                mma_bf16(d[1][nf], a1, bl);
            }
        }
        // pass 2: Xl * Wh
#pragma unroll
        for (int kf = 0; kf < 12; kf++) {
            uint32_t acol = (uint32_t)kf * 16 + acoll;
            uint32_t acp = (acol >> 6) * 16384 + (acol & 63) * 2;
            uint32_t a0[4], a1[4];
            ldsm4(a0, sbase + OFF_AL + sw(arow[0] + acp));
            ldsm4(a1, sbase + OFF_AL + sw(arow[1] + acp));
            uint32_t bcol = (uint32_t)kf * 16 + bcoll;
            uint32_t bcp = (bcol >> 6) * 16384 + (bcol & 63) * 2;
#pragma unroll
            for (int nf = 0; nf < 4; nf++) {
                uint32_t bo = sw(brow[nf] + bcp);
                uint32_t bh[2];
                ldsm2(bh, sbase + OFF_BH + bo);
                mma_bf16(d[0][nf], a0, bh);
                mma_bf16(d[1][nf], a1, bh);
            }
        }

        // ---- C: fragment-native epilogue ----
#pragma unroll
        for (int mb = 0; mb < 2; mb++) {
#pragma unroll
            for (int half = 0; half < 2; half++) {
                int erow = mbase + mb * 16 + gID + half * 8;
                int ok = valid[erow];
                int dst = eRow[erow];
                float part = 0.0f;
#pragma unroll
                for (int nf = 0; nf < 4; nf++) {
                    int col = ncol * 32 + nf * 8 + 2 * tig;
                    float g0 = siluf(d[mb][nf][half * 2 + 0] + b1ps[col]);
                    float g1 = siluf(d[mb][nf][half * 2 + 1] + b1ps[col + 1]);
                    part += g0 * qs[col] + g1 * qs[col + 1];
                    if (ok) redv2(&g_z[(size_t)dst * 128 + col], g0, g1);
                }
                part += __shfl_xor_sync(0xffffffffu, part, 1);
                part += __shfl_xor_sync(0xffffffffu, part, 2);
                if (ok && tig == 0) {
                    float cf = qb4 + part;
                    reds(&g_vagg[dst * 3 + 0], evus[erow * 3 + 0] * cf);
                    reds(&g_vagg[dst * 3 + 1], evus[erow * 3 + 1] * cf);
                    reds(&g_vagg[dst * 3 + 2], evus[erow * 3 + 2] * cf);
                    if (ncol == 0) reds(&g_deg[dst], 1.0f);
                }
            }
        }
        __syncthreads();  // protect tiles + metadata before next tile
    }
}

// ---------------------------------------------------------------- node finalize
__global__ __launch_bounds__(256) void post_kernel(
    const float* __restrict__ s, const float* __restrict__ v,
    const float* __restrict__ mgw2, const float* __restrict__ mgb2,
    const float* __restrict__ upw, const float* __restrict__ upb,
    const float* __restrict__ lng, const float* __restrict__ lnb,
    float* __restrict__ outs, float* __restrict__ outv, int N) {
    __shared__ float mw2t[64][132];
    __shared__ float upwt[64][68];
    __shared__ float zs[4][132];
    __shared__ float xs[4][68];
    __shared__ float sn[4][68];
    const int tid = threadIdx.x;
    for (int idx = tid; idx < 128 * 64; idx += 256) {
        int k = idx >> 6, f = idx & 63;
        mw2t[f][k] = mgw2[idx];
    }
    for (int idx = tid; idx < 64 * 64; idx += 256) {
        int k = idx >> 6, f = idx & 63;
        upwt[f][k] = upw[idx];
    }
    __syncthreads();
    const int slot = tid >> 6, f = tid & 63;
    for (int n0 = blockIdx.x * 4; n0 < N; n0 += gridDim.x * 4) {
        int n = n0 + slot;
        bool ok = (n < N);
        zs[slot][f]      = ok ? g_z[n * 128 + f] : 0.0f;
        zs[slot][64 + f] = ok ? g_z[n * 128 + 64 + f] : 0.0f;
        __syncthreads();
        float degv = ok ? g_deg[n] : 0.0f;
        float acc = degv * mgb2[f];
#pragma unroll 4
        for (int k = 0; k < 128; k += 4) {
            float4 w = *(const float4*)&mw2t[f][k];
            float4 x = *(const float4*)&zs[slot][k];
            acc += w.x * x.x + w.y * x.y + w.z * x.z + w.w * x.w;
        }
        xs[slot][f] = siluf(acc);
        __syncthreads();
        float acc2 = upb[f];
#pragma unroll 4
        for (int k = 0; k < 64; k += 4) {
            float4 w = *(const float4*)&upwt[f][k];
            float4 x = *(const float4*)&xs[slot][k];
            acc2 += w.x * x.x + w.y * x.y + w.z * x.z + w.w * x.w;
        }
        float snew = ok ? (s[n * 64 + f] + acc2) : 0.0f;
        sn[slot][f] = snew;
        __syncthreads();
        float sum = 0.0f, sq = 0.0f;
#pragma unroll 4
        for (int k = 0; k < 64; k += 4) {
            float4 t = *(const float4*)&sn[slot][k];
            sum += t.x + t.y + t.z + t.w;
            sq += t.x * t.x + t.y * t.y + t.z * t.z + t.w * t.w;
        }
        float mu = sum * (1.0f / 64.0f);
        float var = sq * (1.0f / 64.0f) - mu * mu;
        if (ok) {
            outs[n * 64 + f] = (snew - mu) * rsqrtf(var + 1e-5f) * lng[f] + lnb[f];
            if (f < 3) {
                float v0 = v[n * 3 + 0] + g_vagg[n * 3 + 0];
                float v1 = v[n * 3 + 1] + g_vagg[n * 3 + 1];
                float v2 = v[n * 3 + 2] + g_vagg[n * 3 + 2];
                float nrm = sqrtf(v0 * v0 + v1 * v1 + v2 * v2);
                float inv = 1.0f / fmaxf(nrm, 1e-6f);
                float val = (f == 0) ? v0 : (f == 1) ? v1 : v2;
                outv[n * 3 + f] = val * inv;
            }
        }
        __syncthreads();
    }
}

// ---------------------------------------------------------------- launch
extern "C" void kernel_launch(void* const* d_in, const int* in_sizes, int n_in,
                              void* d_out, int out_size) {
    const float* s    = (const float*)d_in[0];
    const float* v    = (const float*)d_in[1];
    const int*   ei   = (const int*)d_in[2];
    const float* ea   = (const float*)d_in[3];
    const float* evu  = (const float*)d_in[4];
    const float* ngw1 = (const float*)d_in[5];
    const float* ngb1 = (const float*)d_in[6];
    const float* ngw2 = (const float*)d_in[7];
    const float* ngb2 = (const float*)d_in[8];
    const float* egw1 = (const float*)d_in[9];
    const float* egb1 = (const float*)d_in[10];
    const float* egw2 = (const float*)d_in[11];
    const float* egb2 = (const float*)d_in[12];
    const float* mgw1 = (const float*)d_in[13];
    const float* mgb1 = (const float*)d_in[14];
    const float* mgw2 = (const float*)d_in[15];
    const float* mgb2 = (const float*)d_in[16];
    const float* pew  = (const float*)d_in[17];
    const float* peb  = (const float*)d_in[18];
    const float* upw  = (const float*)d_in[19];
    const float* upb  = (const float*)d_in[20];
    const float* lng  = (const float*)d_in[21];
    const float* lnb  = (const float*)d_in[22];

    const int N = in_sizes[0] / 64;
    const int E = in_sizes[2] / 2;

    float* outs = (float*)d_out;
    float* outv = outs + (size_t)N * 64;

    int nsm = 148;
    cudaDeviceGetAttribute(&nsm, cudaDevAttrMultiProcessorCount, 0);

    zero_kernel<<<512, 256>>>(N * 128, N * 3, N);
    pre_kernel<<<1184, 256>>>(s, ngw1, N);
    preW_kernel<<<128, 256>>>(ngw2, ngb2, egw2, egb2, mgw1, mgb1, mgw2, mgb2, pew, peb);

    cudaFuncSetAttribute(edge_kernel, cudaFuncAttributeMaxDynamicSharedMemorySize,
                         EDGE_SMEM_TOTAL);
    edge_kernel<<<nsm, 512, EDGE_SMEM_TOTAL>>>(
        v, ei, ea, evu, ngw1, ngb1, egw1, egb1, N, E);

    post_kernel<<<1184, 256>>>(s, v, mgw2, mgb2, upw, upb, lng, lnb, outs, outv, N);
}